// round 9
// baseline (speedup 1.0000x reference)
#include <cuda_runtime.h>
#include <cuda_bf16.h>
#include <cstdint>

// Neural ODE RK4 on tensor cores via mma.sync (sm_100-safe).
// B=4096, D=H=256, 100 RK4 steps. dx/dt = tanh(x@W1+b1)@W2 + b2.
// GEMMs in bf16 hi/lo split: D = Ah*Bh + Ah*Bl + Al*Bh (fp32 accum).
//
// R9: 296 persistent CTAs x 16 rows, TWO CTAs per SM (launch_bounds(256,2))
// so one CTA's cp.async/barrier stalls are hidden by the other CTA's MMAs.
// k32 W chunks double-buffered; A (x / tanh) as bf16 hi/lo in smem
// (528B-padded rows, conflict-free ldmatrix). Rows padded to 4736: reads
// clamp to row 4095, trajectory writes are guarded.
//
// Output = flattened tuple (times[101], traj[101,4096,256]); traj starts at
// byte offset 404 -> scalar 4B global stores for trajectory.

#define NSTEPS   100
#define BROWS    4096
#define DIM      256
#define MROWS    16
#define NCTAS    296
#define NTHREADS 256

#define ASTRIDE  528                 // bytes per padded 256-bf16 row
#define A_LO     8448                // 16 rows * 528
#define PARTB    16896               // 32 k-rows * 528 (one hi or lo part)
#define CHUNKB   (2 * PARTB)         // 33792
#define W_OFF    16896               // after A hi+lo
#define B1_OFF   (W_OFF + 2 * CHUNKB)          // 84480
#define B2_OFF   (B1_OFF + 1024)
#define SMEM_BYTES (B2_OFF + 1024)             // 86528 (x2 CTAs = 173KB/SM)

#define PART_EL  8448                // bf16 elements per part
__device__ __align__(16) __nv_bfloat16 g_Wp[2 * 8 * 2 * PART_EL]; // [mat][chunk][part]

// ---------------- helpers ----------------
__device__ __forceinline__ uint32_t smem_u32(const void* p) {
    uint32_t a;
    asm("{ .reg .u64 t; cvta.to.shared.u64 t, %1; cvt.u32.u64 %0, t; }"
        : "=r"(a) : "l"(p));
    return a;
}
__device__ __forceinline__ void ldsm_x4(uint32_t r[4], uint32_t a) {
    asm volatile("ldmatrix.sync.aligned.m8n8.x4.shared.b16 {%0,%1,%2,%3}, [%4];"
                 : "=r"(r[0]), "=r"(r[1]), "=r"(r[2]), "=r"(r[3]) : "r"(a));
}
__device__ __forceinline__ void ldsm_x2t(uint32_t r[2], uint32_t a) {
    asm volatile("ldmatrix.sync.aligned.m8n8.x2.trans.shared.b16 {%0,%1}, [%2];"
                 : "=r"(r[0]), "=r"(r[1]) : "r"(a));
}
__device__ __forceinline__ void mma16816(float c[4], const uint32_t a[4],
                                         const uint32_t b[2]) {
    asm volatile("mma.sync.aligned.m16n8k16.row.col.f32.bf16.bf16.f32 "
                 "{%0,%1,%2,%3}, {%4,%5,%6,%7}, {%8,%9}, {%0,%1,%2,%3};"
                 : "+f"(c[0]), "+f"(c[1]), "+f"(c[2]), "+f"(c[3])
                 : "r"(a[0]), "r"(a[1]), "r"(a[2]), "r"(a[3]),
                   "r"(b[0]), "r"(b[1]));
}
__device__ __forceinline__ void splitstore(uint32_t ahi, uint32_t alo,
                                           float va, float vb) {
    __nv_bfloat162 h = __floats2bfloat162_rn(va, vb);
    float2 hf = __bfloat1622float2(h);
    __nv_bfloat162 l = __floats2bfloat162_rn(va - hf.x, vb - hf.y);
    uint32_t hu = *reinterpret_cast<uint32_t*>(&h);
    uint32_t lu = *reinterpret_cast<uint32_t*>(&l);
    asm volatile("st.shared.b32 [%0], %1;" :: "r"(ahi), "r"(hu) : "memory");
    asm volatile("st.shared.b32 [%0], %1;" :: "r"(alo), "r"(lu) : "memory");
}

// ---------------- repack: W[k][n] fp32 -> hi/lo bf16, k32 chunks ----------
__global__ void repack_kernel(const float* __restrict__ W1,
                              const float* __restrict__ W2)
{
    int t = blockIdx.x * blockDim.x + threadIdx.x;
    if (t >= 2 * DIM * DIM) return;
    int mat = t >> 16;
    int k   = (t >> 8) & 255;
    int n   = t & 255;
    float w = (mat ? W2 : W1)[k * DIM + n];
    __nv_bfloat16 h = __float2bfloat16(w);
    __nv_bfloat16 l = __float2bfloat16(w - __bfloat162float(h));
    int chunk = k >> 5;
    int idx = (mat * 8 + chunk) * 2 * PART_EL + (k & 31) * 264 + n;
    g_Wp[idx]           = h;
    g_Wp[idx + PART_EL] = l;
}

// ---------------- main kernel ----------------
extern __shared__ char smem_raw[];

__device__ __forceinline__ void cp_chunk(int mat, int c, int buf,
                                         uint32_t sb, int tid)
{
    uint32_t dst = sb + W_OFF + (uint32_t)buf * CHUNKB;
    const char* src = reinterpret_cast<const char*>(g_Wp)
                    + (size_t)(mat * 8 + c) * CHUNKB;
    for (int i = tid; i < CHUNKB / 16; i += NTHREADS) {
        asm volatile("cp.async.cg.shared.global [%0], [%1], 16;\n"
                     :: "r"(dst + (uint32_t)i * 16u), "l"(src + (size_t)i * 16));
    }
    asm volatile("cp.async.commit_group;\n" ::: "memory");
}

// one k32 chunk of the M16 x N32 (per-warp) GEMM, 3-term bf16 split.
// akoff = byte offset of this chunk's k slice within the A row (kchunk*64).
__device__ __forceinline__ void compute_chunk(float c[4][4], uint32_t sb,
                                              int buf, uint32_t aoff,
                                              uint32_t akoff, uint32_t boff)
{
    uint32_t wb = sb + W_OFF + (uint32_t)buf * CHUNKB;
    #pragma unroll
    for (int ks = 0; ks < 2; ks++) {
        uint32_t ab = sb + aoff + akoff + (uint32_t)ks * 32u;
        uint32_t ah[4], al[4];
        ldsm_x4(ah, ab);
        ldsm_x4(al, ab + A_LO);

        uint32_t bb = wb + boff + (uint32_t)ks * 16u * ASTRIDE;
        uint32_t bh[4][2], bl[4][2];
        #pragma unroll
        for (int nt = 0; nt < 4; nt++) {
            ldsm_x2t(bh[nt], bb + (uint32_t)nt * 16u);
            ldsm_x2t(bl[nt], bb + PARTB + (uint32_t)nt * 16u);
        }
        #pragma unroll
        for (int nt = 0; nt < 4; nt++) {
            mma16816(c[nt], ah, bh[nt]);
            mma16816(c[nt], ah, bl[nt]);
            mma16816(c[nt], al, bh[nt]);
        }
    }
}

__global__ void __launch_bounds__(NTHREADS, 2)
ode_tc_kernel(const float* __restrict__ x0, const float* __restrict__ tspan,
              const float* __restrict__ b1, const float* __restrict__ b2,
              float* __restrict__ times, float* __restrict__ traj)
{
    uint32_t sb = smem_u32(smem_raw);
    float* b1s = reinterpret_cast<float*>(smem_raw + B1_OFF);
    float* b2s = reinterpret_cast<float*>(smem_raw + B2_OFF);

    const int tid  = threadIdx.x;
    const int lane = tid & 31;
    const int w    = tid >> 5;
    const int r0   = lane >> 2;
    const int cp2  = (lane & 3) * 2;
    const int row_base = blockIdx.x * MROWS;   // up to 4720 (padded)

    // ldmatrix per-thread byte offsets
    const uint32_t aoff = (uint32_t)(((lane & 7) + ((lane >> 3) & 1) * 8) * ASTRIDE
                                     + (lane >> 4) * 16);
    const uint32_t boff = (uint32_t)((lane & 15) * ASTRIDE + w * 64);

    // prime the cp.async pipeline: mat0 chunk0 -> buf0
    cp_chunk(0, 0, 0, sb, tid);

    // biases -> smem (visible to epilogues after the first chunk barriers)
    if (tid < 256) { b1s[tid] = b1[tid]; b2s[tid] = b2[tid]; }

    float c[4][4], xv[4][4], kc[4][4];

    // init: x0 -> registers + A tiles (hi/lo) + trajectory frame 0
    #pragma unroll
    for (int nt = 0; nt < 4; nt++) {
        int col = w * 32 + nt * 8 + cp2;
        #pragma unroll
        for (int rh = 0; rh < 2; rh++) {
            int row = r0 + rh * 8;
            int grow = row_base + row;
            int crow = (grow < BROWS) ? grow : (BROWS - 1);
            long long g = (long long)crow * DIM + col;
            float v0 = x0[g], v1 = x0[g + 1];
            xv[nt][rh * 2]     = v0;
            xv[nt][rh * 2 + 1] = v1;
            if (grow < BROWS) { traj[g] = v0; traj[g + 1] = v1; }
            uint32_t ao = sb + (uint32_t)(row * ASTRIDE + col * 2);
            splitstore(ao, ao + A_LO, v0, v1);
        }
        float bv0 = b1[col], bv1 = b1[col + 1];
        c[nt][0] = bv0; c[nt][1] = bv1; c[nt][2] = bv0; c[nt][3] = bv1;
    }

    if (times != nullptr && blockIdx.x == 0) {
        float t0 = tspan[0];
        for (int i = tid; i <= NSTEPS; i += NTHREADS)
            times[i] = t0 + 0.01f * (float)i;
    }

    const float halfdt = 0.005f;
    const float dt     = 0.01f;
    const float sixth  = (float)(0.01 / 6.0);
    const long long frame = (long long)BROWS * DIM;

    #pragma unroll 1
    for (int step = 0; step < NSTEPS; step++) {
        #pragma unroll 1
        for (int s = 0; s < 4; s++) {
            // -------- one vf eval: 16 k32 chunks (8 x W1, 8 x W2) --------
            #pragma unroll 1
            for (int t = 0; t < 16; t++) {
                int nx = (t + 1) & 15;
                cp_chunk(nx >> 3, nx & 7, (t + 1) & 1, sb, tid);
                asm volatile("cp.async.wait_group 1;\n" ::: "memory");
                __syncthreads();                 // chunk resident, A visible
                compute_chunk(c, sb, t & 1, aoff,
                              (uint32_t)(t & 7) * 64u, boff);
                __syncthreads();                 // done with buf + A reads

                if (t == 7) {                    // epi1: h = tanh(D) -> A
                    #pragma unroll
                    for (int nt = 0; nt < 4; nt++) {
                        int col = w * 32 + nt * 8 + cp2;
                        #pragma unroll
                        for (int rh = 0; rh < 2; rh++) {
                            int row = r0 + rh * 8;
                            float v0 = tanhf(c[nt][rh * 2]);
                            float v1 = tanhf(c[nt][rh * 2 + 1]);
                            uint32_t ao = sb + (uint32_t)(row * ASTRIDE + col * 2);
                            splitstore(ao, ao + A_LO, v0, v1);
                        }
                        float bv0 = b2s[col], bv1 = b2s[col + 1];
                        c[nt][0] = bv0; c[nt][1] = bv1;
                        c[nt][2] = bv0; c[nt][3] = bv1;
                    }
                }
            }

            // -------- epi2: k ready in c; RK4 combine; next A --------
            #pragma unroll
            for (int nt = 0; nt < 4; nt++) {
                int col = w * 32 + nt * 8 + cp2;
                #pragma unroll
                for (int rh = 0; rh < 2; rh++) {
                    int row = r0 + rh * 8;
                    float v[2];
                    #pragma unroll
                    for (int j = 0; j < 2; j++) {
                        int e = rh * 2 + j;
                        float k = c[nt][e];
                        float x = xv[nt][e];
                        if (s == 0) {
                            kc[nt][e] = k;
                            v[j] = x + halfdt * k;
                        } else if (s == 1) {
                            kc[nt][e] += 2.0f * k;
                            v[j] = x + halfdt * k;
                        } else if (s == 2) {
                            kc[nt][e] += 2.0f * k;
                            v[j] = x + dt * k;
                        } else {
                            float xn = x + sixth * (kc[nt][e] + k);
                            xv[nt][e] = xn;
                            v[j] = xn;
                        }
                    }
                    uint32_t ao = sb + (uint32_t)(row * ASTRIDE + col * 2);
                    splitstore(ao, ao + A_LO, v[0], v[1]);
                    if (s == 3 && row_base + row < BROWS) {
                        long long g = (long long)(step + 1) * frame
                                    + (long long)(row_base + row) * DIM + col;
                        traj[g]     = v[0];
                        traj[g + 1] = v[1];
                    }
                }
                float bv0 = b1s[col], bv1 = b1s[col + 1];
                c[nt][0] = bv0; c[nt][1] = bv1;
                c[nt][2] = bv0; c[nt][3] = bv1;
            }
            // next chunk's pre-compute __syncthreads orders these A writes
        }
    }
}

extern "C" void kernel_launch(void* const* d_in, const int* in_sizes, int n_in,
                              void* d_out, int out_size)
{
    const float* x0    = (const float*)d_in[0];
    const float* tspan = (const float*)d_in[1];
    const float* W1    = (const float*)d_in[2];
    const float* b1    = (const float*)d_in[3];
    const float* W2    = (const float*)d_in[4];
    const float* b2    = (const float*)d_in[5];

    float* out = (float*)d_out;
    const long long traj_elems = (long long)(NSTEPS + 1) * BROWS * DIM;
    float* times = nullptr;
    float* traj  = out;
    if ((long long)out_size >= traj_elems + (NSTEPS + 1)) {
        times = out;
        traj  = out + (NSTEPS + 1);
    }

    repack_kernel<<<512, 256>>>(W1, W2);

    cudaFuncSetAttribute(ode_tc_kernel,
                         cudaFuncAttributeMaxDynamicSharedMemorySize, SMEM_BYTES);
    ode_tc_kernel<<<NCTAS, NTHREADS, SMEM_BYTES>>>(x0, tspan, b1, b2, times, traj);
}

// round 10
// speedup vs baseline: 1.1581x; 1.1581x over previous
#include <cuda_runtime.h>
#include <cuda_bf16.h>
#include <cstdint>

// Neural ODE RK4 on tensor cores via mma.sync (sm_100-safe).
// B=4096, D=H=256, 100 RK4 steps. dx/dt = tanh(x@W1+b1)@W2 + b2.
// GEMMs in bf16 hi/lo split: D = Ah*Bh + Ah*Bl + Al*Bh (fp32 accum).
//
// R10 = R8 (5050us, 128 CTAs x 32 rows, k64 double-buffered chunks) with ONE
// change: MMA issue order interleaved across all 8 accumulator fragments so
// consecutive HMMAs never RAW-depend on the same accumulator (chain distance
// 1 -> 8). R8/R9 both capped tensor at ~45% from this dependency chain.
//
// Output = flattened tuple (times[101], traj[101,4096,256]); traj starts at
// byte offset 404 -> scalar 4B global stores for trajectory.

#define NSTEPS   100
#define BROWS    4096
#define DIM      256
#define MROWS    32
#define NCTAS    128
#define NTHREADS 256

#define ASTRIDE  528                 // bytes per padded 256-bf16 row
#define PART_EL  16896               // 64 * 264 bf16 elements per k64 part
#define PARTB    (64 * ASTRIDE)      // 33792 B
#define CHUNKB   (2 * PARTB)         // hi+lo, 67584 B
#define A_HI     0
#define A_LO     16896               // bytes: 32 rows * 528
#define W_OFF    33792
#define SMEM_BYTES (W_OFF + 2 * CHUNKB)   // 168960

__device__ __align__(16) __nv_bfloat16 g_Wp[2 * 4 * 2 * PART_EL]; // [mat][chunk][part]

// ---------------- helpers ----------------
__device__ __forceinline__ uint32_t smem_u32(const void* p) {
    uint32_t a;
    asm("{ .reg .u64 t; cvta.to.shared.u64 t, %1; cvt.u32.u64 %0, t; }"
        : "=r"(a) : "l"(p));
    return a;
}
__device__ __forceinline__ void ldsm_x4(uint32_t r[4], uint32_t a) {
    asm volatile("ldmatrix.sync.aligned.m8n8.x4.shared.b16 {%0,%1,%2,%3}, [%4];"
                 : "=r"(r[0]), "=r"(r[1]), "=r"(r[2]), "=r"(r[3]) : "r"(a));
}
__device__ __forceinline__ void ldsm_x2t(uint32_t r[2], uint32_t a) {
    asm volatile("ldmatrix.sync.aligned.m8n8.x2.trans.shared.b16 {%0,%1}, [%2];"
                 : "=r"(r[0]), "=r"(r[1]) : "r"(a));
}
__device__ __forceinline__ void mma16816(float c[4], const uint32_t a[4],
                                         const uint32_t b[2]) {
    asm volatile("mma.sync.aligned.m16n8k16.row.col.f32.bf16.bf16.f32 "
                 "{%0,%1,%2,%3}, {%4,%5,%6,%7}, {%8,%9}, {%0,%1,%2,%3};"
                 : "+f"(c[0]), "+f"(c[1]), "+f"(c[2]), "+f"(c[3])
                 : "r"(a[0]), "r"(a[1]), "r"(a[2]), "r"(a[3]),
                   "r"(b[0]), "r"(b[1]));
}
// split (va, vb) into bf16 hi/lo pairs and store into A tiles
__device__ __forceinline__ void splitstore(uint32_t ahi, uint32_t alo,
                                           float va, float vb) {
    __nv_bfloat162 h = __floats2bfloat162_rn(va, vb);
    float2 hf = __bfloat1622float2(h);
    __nv_bfloat162 l = __floats2bfloat162_rn(va - hf.x, vb - hf.y);
    uint32_t hu = *reinterpret_cast<uint32_t*>(&h);
    uint32_t lu = *reinterpret_cast<uint32_t*>(&l);
    asm volatile("st.shared.b32 [%0], %1;" :: "r"(ahi), "r"(hu) : "memory");
    asm volatile("st.shared.b32 [%0], %1;" :: "r"(alo), "r"(lu) : "memory");
}

// ---------------- repack: W[k][n] fp32 -> hi/lo bf16, padded rows ----------
__global__ void repack_kernel(const float* __restrict__ W1,
                              const float* __restrict__ W2)
{
    int t = blockIdx.x * blockDim.x + threadIdx.x;
    if (t >= 2 * DIM * DIM) return;
    int mat = t >> 16;
    int k   = (t >> 8) & 255;
    int n   = t & 255;
    float w = (mat ? W2 : W1)[k * DIM + n];
    __nv_bfloat16 h = __float2bfloat16(w);
    __nv_bfloat16 l = __float2bfloat16(w - __bfloat162float(h));
    int chunk = k >> 6;
    int idx = (mat * 4 + chunk) * 2 * PART_EL + (k & 63) * 264 + n;
    g_Wp[idx]           = h;
    g_Wp[idx + PART_EL] = l;
}

// ---------------- main kernel ----------------
extern __shared__ char smem_raw[];

__device__ __forceinline__ void cp_chunk(int mat, int c, int buf,
                                         uint32_t sb, int tid)
{
    uint32_t dst = sb + W_OFF + (uint32_t)buf * CHUNKB;
    const char* src = reinterpret_cast<const char*>(g_Wp)
                    + (size_t)(mat * 4 + c) * CHUNKB;
    for (int i = tid; i < CHUNKB / 16; i += NTHREADS) {
        asm volatile("cp.async.cg.shared.global [%0], [%1], 16;\n"
                     :: "r"(dst + (uint32_t)i * 16u), "l"(src + (size_t)i * 16));
    }
    asm volatile("cp.async.commit_group;\n" ::: "memory");
}

// one k64 chunk of the M32 x N32 (per-warp) GEMM, 3-term bf16 split.
// akoff = byte offset of this chunk's k64 slice within the A row (kchunk*128).
// MMA order: term-major so consecutive HMMAs touch 8 distinct accumulators.
__device__ __forceinline__ void compute_chunk(float c[2][4][4], uint32_t sb,
                                              int buf, uint32_t aoff,
                                              uint32_t akoff, uint32_t boff)
{
    uint32_t wb = sb + W_OFF + (uint32_t)buf * CHUNKB;
    #pragma unroll
    for (int ks = 0; ks < 4; ks++) {
        uint32_t ab = sb + A_HI + aoff + akoff + (uint32_t)ks * 32u;
        uint32_t ah[2][4], al[2][4];
        ldsm_x4(ah[0], ab);
        ldsm_x4(ah[1], ab + 16u * ASTRIDE);
        ldsm_x4(al[0], ab + (A_LO - A_HI));
        ldsm_x4(al[1], ab + (A_LO - A_HI) + 16u * ASTRIDE);

        uint32_t bb = wb + boff + (uint32_t)ks * 16u * ASTRIDE;
        uint32_t bh[4][2], bl[4][2];
        #pragma unroll
        for (int nt = 0; nt < 4; nt++) {
            ldsm_x2t(bh[nt], bb + (uint32_t)nt * 16u);
            ldsm_x2t(bl[nt], bb + PARTB + (uint32_t)nt * 16u);
        }
        // term 1: Ah * Bh over all 8 fragments (no back-to-back RAW)
        #pragma unroll
        for (int mt = 0; mt < 2; mt++)
            #pragma unroll
            for (int nt = 0; nt < 4; nt++)
                mma16816(c[mt][nt], ah[mt], bh[nt]);
        // term 2: Ah * Bl
        #pragma unroll
        for (int mt = 0; mt < 2; mt++)
            #pragma unroll
            for (int nt = 0; nt < 4; nt++)
                mma16816(c[mt][nt], ah[mt], bl[nt]);
        // term 3: Al * Bh
        #pragma unroll
        for (int mt = 0; mt < 2; mt++)
            #pragma unroll
            for (int nt = 0; nt < 4; nt++)
                mma16816(c[mt][nt], al[mt], bh[nt]);
    }
}

__global__ void __launch_bounds__(NTHREADS, 1)
ode_tc_kernel(const float* __restrict__ x0, const float* __restrict__ tspan,
              const float* __restrict__ b1, const float* __restrict__ b2,
              float* __restrict__ times, float* __restrict__ traj)
{
    uint32_t sb = smem_u32(smem_raw);
    const int tid  = threadIdx.x;
    const int lane = tid & 31;
    const int w    = tid >> 5;
    const int r0   = lane >> 2;
    const int cp2  = (lane & 3) * 2;
    const int row_base = blockIdx.x * MROWS;

    // ldmatrix per-thread byte offsets
    const uint32_t aoff = (uint32_t)(((lane & 7) + ((lane >> 3) & 1) * 8) * ASTRIDE
                                     + (lane >> 4) * 16);
    const uint32_t boff = (uint32_t)((lane & 15) * ASTRIDE + w * 64);

    // prime the cp.async pipeline: mat0 chunk0 -> buf0
    cp_chunk(0, 0, 0, sb, tid);

    // biases for this thread's fixed columns
    float b1v[4][2], b2v[4][2];
    #pragma unroll
    for (int nt = 0; nt < 4; nt++) {
        int col = w * 32 + nt * 8 + cp2;
        b1v[nt][0] = b1[col];     b1v[nt][1] = b1[col + 1];
        b2v[nt][0] = b2[col];     b2v[nt][1] = b2[col + 1];
    }

    float c[2][4][4], xv[2][4][4], kc[2][4][4];

    // init: x0 -> registers + A tiles (hi/lo) + trajectory frame 0
    #pragma unroll
    for (int mt = 0; mt < 2; mt++)
        #pragma unroll
        for (int nt = 0; nt < 4; nt++) {
            int col = w * 32 + nt * 8 + cp2;
            #pragma unroll
            for (int rh = 0; rh < 2; rh++) {
                int row = mt * 16 + r0 + rh * 8;
                long long g = (long long)(row_base + row) * DIM + col;
                float v0 = x0[g], v1 = x0[g + 1];
                xv[mt][nt][rh * 2]     = v0;
                xv[mt][nt][rh * 2 + 1] = v1;
                traj[g] = v0; traj[g + 1] = v1;
                uint32_t ao = sb + (uint32_t)(row * ASTRIDE + col * 2);
                splitstore(ao + A_HI, ao + A_LO, v0, v1);
            }
            #pragma unroll
            for (int e = 0; e < 4; e++) c[mt][nt][e] = b1v[nt][e & 1];
        }

    if (times != nullptr && blockIdx.x == 0) {
        float t0 = tspan[0];
        for (int i = tid; i <= NSTEPS; i += NTHREADS)
            times[i] = t0 + 0.01f * (float)i;
    }

    const float halfdt = 0.005f;
    const float dt     = 0.01f;
    const float sixth  = (float)(0.01 / 6.0);
    const long long frame = (long long)BROWS * DIM;

    #pragma unroll 1
    for (int step = 0; step < NSTEPS; step++) {
        #pragma unroll 1
        for (int s = 0; s < 4; s++) {
            // -------- one vf eval: 8 k64 chunks (4 x W1, 4 x W2) --------
            #pragma unroll 1
            for (int t = 0; t < 8; t++) {
                int imat = (t < 3) ? 0 : (t < 7) ? 1 : 0;
                int ic   = (t < 3) ? t + 1 : (t < 7) ? t - 3 : 0;
                cp_chunk(imat, ic, (t + 1) & 1, sb, tid);
                asm volatile("cp.async.wait_group 1;\n" ::: "memory");
                __syncthreads();                 // chunk resident, A visible
                compute_chunk(c, sb, t & 1, aoff,
                              (uint32_t)(t & 3) * 128u, boff);
                __syncthreads();                 // done with buf + A reads

                if (t == 3) {                    // epi1: h = tanh(D) -> A
                    #pragma unroll
                    for (int mt = 0; mt < 2; mt++)
                        #pragma unroll
                        for (int nt = 0; nt < 4; nt++) {
                            int col = w * 32 + nt * 8 + cp2;
                            #pragma unroll
                            for (int rh = 0; rh < 2; rh++) {
                                int row = mt * 16 + r0 + rh * 8;
                                float v0 = tanhf(c[mt][nt][rh * 2]);
                                float v1 = tanhf(c[mt][nt][rh * 2 + 1]);
                                uint32_t ao = sb + (uint32_t)(row * ASTRIDE + col * 2);
                                splitstore(ao + A_HI, ao + A_LO, v0, v1);
                            }
                            #pragma unroll
                            for (int e = 0; e < 4; e++)
                                c[mt][nt][e] = b2v[nt][e & 1];
                        }
                }
            }

            // -------- epi2: k ready in c; RK4 combine; next A --------
            #pragma unroll
            for (int mt = 0; mt < 2; mt++)
                #pragma unroll
                for (int nt = 0; nt < 4; nt++) {
                    int col = w * 32 + nt * 8 + cp2;
                    #pragma unroll
                    for (int rh = 0; rh < 2; rh++) {
                        int row = mt * 16 + r0 + rh * 8;
                        float v[2];
                        #pragma unroll
                        for (int j = 0; j < 2; j++) {
                            int e = rh * 2 + j;
                            float k = c[mt][nt][e];
                            float x = xv[mt][nt][e];
                            if (s == 0) {
                                kc[mt][nt][e] = k;
                                v[j] = x + halfdt * k;
                            } else if (s == 1) {
                                kc[mt][nt][e] += 2.0f * k;
                                v[j] = x + halfdt * k;
                            } else if (s == 2) {
                                kc[mt][nt][e] += 2.0f * k;
                                v[j] = x + dt * k;
                            } else {
                                float xn = x + sixth * (kc[mt][nt][e] + k);
                                xv[mt][nt][e] = xn;
                                v[j] = xn;
                            }
                        }
                        uint32_t ao = sb + (uint32_t)(row * ASTRIDE + col * 2);
                        splitstore(ao + A_HI, ao + A_LO, v[0], v[1]);
                        if (s == 3) {
                            long long g = (long long)(step + 1) * frame
                                        + (long long)(row_base + row) * DIM + col;
                            traj[g]     = v[0];
                            traj[g + 1] = v[1];
                        }
                    }
                    #pragma unroll
                    for (int e = 0; e < 4; e++)
                        c[mt][nt][e] = b1v[nt][e & 1];
                }
            // next chunk's pre-compute __syncthreads orders these A writes
        }
    }
}

extern "C" void kernel_launch(void* const* d_in, const int* in_sizes, int n_in,
                              void* d_out, int out_size)
{
    const float* x0    = (const float*)d_in[0];
    const float* tspan = (const float*)d_in[1];
    const float* W1    = (const float*)d_in[2];
    const float* b1    = (const float*)d_in[3];
    const float* W2    = (const float*)d_in[4];
    const float* b2    = (const float*)d_in[5];

    float* out = (float*)d_out;
    const long long traj_elems = (long long)(NSTEPS + 1) * BROWS * DIM;
    float* times = nullptr;
    float* traj  = out;
    if ((long long)out_size >= traj_elems + (NSTEPS + 1)) {
        times = out;
        traj  = out + (NSTEPS + 1);
    }

    repack_kernel<<<512, 256>>>(W1, W2);

    cudaFuncSetAttribute(ode_tc_kernel,
                         cudaFuncAttributeMaxDynamicSharedMemorySize, SMEM_BYTES);
    ode_tc_kernel<<<NCTAS, NTHREADS, SMEM_BYTES>>>(x0, tspan, b1, b2, times, traj);
}

// round 11
// speedup vs baseline: 1.4632x; 1.2635x over previous
#include <cuda_runtime.h>
#include <cuda_fp16.h>
#include <cstdint>

// Neural ODE RK4 on tensor cores via mma.sync (sm_100-safe).
// B=4096, D=H=256, 100 RK4 steps. dx/dt = tanh(x@W1+b1)@W2 + b2.
//
// R11: fp16 TWO-term split (was bf16 3-term). Measured R8/R9/R10 all pin at
// 512 FMA/cyc/SM = the sm_100 mma.sync issue ceiling (1 HMMA / 16cyc / SMSP),
// so the only lever is fewer MMAs: D = x_f16 * Wh + x_f16 * Wl, with W
// pre-split hi/lo fp16 (exact to 2^-22) and x rounded to fp16 (2^-11,
// pseudo-random across steps -> cancels; measured amplification ~0.35x).
//
// 128 persistent CTAs x 32 rows; 8 warps; warp w owns N[w*32..) slab.
// A (x / tanh) single fp16 in smem (528B-padded rows). W streamed as
// double-buffered k64 chunks via cp.async.
//
// Output = flattened tuple (times[101], traj[101,4096,256]); traj starts at
// byte offset 404 -> scalar 4B global stores for trajectory.

#define NSTEPS   100
#define BROWS    4096
#define DIM      256
#define MROWS    32
#define NCTAS    128
#define NTHREADS 256

#define ASTRIDE  528                 // bytes per padded 256-fp16 row
#define PART_EL  16896               // 64 * 264 fp16 elements per k64 part
#define PARTB    (64 * ASTRIDE)      // 33792 B
#define CHUNKB   (2 * PARTB)         // hi+lo, 67584 B
#define W_OFF    16896               // A = 32 rows * 528 B (single fp16)
#define SMEM_BYTES (W_OFF + 2 * CHUNKB)   // 152064

__device__ __align__(16) __half g_Wp[2 * 4 * 2 * PART_EL]; // [mat][chunk][part]

// ---------------- helpers ----------------
__device__ __forceinline__ uint32_t smem_u32(const void* p) {
    uint32_t a;
    asm("{ .reg .u64 t; cvta.to.shared.u64 t, %1; cvt.u32.u64 %0, t; }"
        : "=r"(a) : "l"(p));
    return a;
}
__device__ __forceinline__ void ldsm_x4(uint32_t r[4], uint32_t a) {
    asm volatile("ldmatrix.sync.aligned.m8n8.x4.shared.b16 {%0,%1,%2,%3}, [%4];"
                 : "=r"(r[0]), "=r"(r[1]), "=r"(r[2]), "=r"(r[3]) : "r"(a));
}
__device__ __forceinline__ void ldsm_x2t(uint32_t r[2], uint32_t a) {
    asm volatile("ldmatrix.sync.aligned.m8n8.x2.trans.shared.b16 {%0,%1}, [%2];"
                 : "=r"(r[0]), "=r"(r[1]) : "r"(a));
}
__device__ __forceinline__ void mma16816(float c[4], const uint32_t a[4],
                                         const uint32_t b[2]) {
    asm volatile("mma.sync.aligned.m16n8k16.row.col.f32.f16.f16.f32 "
                 "{%0,%1,%2,%3}, {%4,%5,%6,%7}, {%8,%9}, {%0,%1,%2,%3};"
                 : "+f"(c[0]), "+f"(c[1]), "+f"(c[2]), "+f"(c[3])
                 : "r"(a[0]), "r"(a[1]), "r"(a[2]), "r"(a[3]),
                   "r"(b[0]), "r"(b[1]));
}
// round (va, vb) to fp16 pair and store as one b32 into the A tile
__device__ __forceinline__ void hstore(uint32_t addr, float va, float vb) {
    __half2 h = __floats2half2_rn(va, vb);
    uint32_t u = *reinterpret_cast<uint32_t*>(&h);
    asm volatile("st.shared.b32 [%0], %1;" :: "r"(addr), "r"(u) : "memory");
}

// ---------------- repack: W[k][n] fp32 -> hi/lo fp16, padded rows ----------
__global__ void repack_kernel(const float* __restrict__ W1,
                              const float* __restrict__ W2)
{
    int t = blockIdx.x * blockDim.x + threadIdx.x;
    if (t >= 2 * DIM * DIM) return;
    int mat = t >> 16;
    int k   = (t >> 8) & 255;
    int n   = t & 255;
    float w = (mat ? W2 : W1)[k * DIM + n];
    __half h = __float2half_rn(w);
    __half l = __float2half_rn(w - __half2float(h));
    int chunk = k >> 6;
    int idx = (mat * 4 + chunk) * 2 * PART_EL + (k & 63) * 264 + n;
    g_Wp[idx]           = h;
    g_Wp[idx + PART_EL] = l;
}

// ---------------- main kernel ----------------
extern __shared__ char smem_raw[];

__device__ __forceinline__ void cp_chunk(int mat, int c, int buf,
                                         uint32_t sb, int tid)
{
    uint32_t dst = sb + W_OFF + (uint32_t)buf * CHUNKB;
    const char* src = reinterpret_cast<const char*>(g_Wp)
                    + (size_t)(mat * 4 + c) * CHUNKB;
    for (int i = tid; i < CHUNKB / 16; i += NTHREADS) {
        asm volatile("cp.async.cg.shared.global [%0], [%1], 16;\n"
                     :: "r"(dst + (uint32_t)i * 16u), "l"(src + (size_t)i * 16));
    }
    asm volatile("cp.async.commit_group;\n" ::: "memory");
}

// one k64 chunk of the M32 x N32 (per-warp) GEMM, 2-term fp16 split.
// akoff = byte offset of this chunk's k64 slice within the A row (kchunk*128).
__device__ __forceinline__ void compute_chunk(float c[2][4][4], uint32_t sb,
                                              int buf, uint32_t aoff,
                                              uint32_t akoff, uint32_t boff)
{
    uint32_t wb = sb + W_OFF + (uint32_t)buf * CHUNKB;
    #pragma unroll
    for (int ks = 0; ks < 4; ks++) {
        uint32_t ab = sb + aoff + akoff + (uint32_t)ks * 32u;
        uint32_t a0[4], a1[4];
        ldsm_x4(a0, ab);
        ldsm_x4(a1, ab + 16u * ASTRIDE);

        uint32_t bb = wb + boff + (uint32_t)ks * 16u * ASTRIDE;
        uint32_t bh[4][2], bl[4][2];
        #pragma unroll
        for (int nt = 0; nt < 4; nt++) {
            ldsm_x2t(bh[nt], bb + (uint32_t)nt * 16u);
            ldsm_x2t(bl[nt], bb + PARTB + (uint32_t)nt * 16u);
        }
        // term 1: x * Wh  (term-major: 8 distinct accumulators in a row)
        #pragma unroll
        for (int nt = 0; nt < 4; nt++) {
            mma16816(c[0][nt], a0, bh[nt]);
            mma16816(c[1][nt], a1, bh[nt]);
        }
        // term 2: x * Wl
        #pragma unroll
        for (int nt = 0; nt < 4; nt++) {
            mma16816(c[0][nt], a0, bl[nt]);
            mma16816(c[1][nt], a1, bl[nt]);
        }
    }
}

__global__ void __launch_bounds__(NTHREADS, 1)
ode_tc_kernel(const float* __restrict__ x0, const float* __restrict__ tspan,
              const float* __restrict__ b1, const float* __restrict__ b2,
              float* __restrict__ times, float* __restrict__ traj)
{
    uint32_t sb = smem_u32(smem_raw);
    const int tid  = threadIdx.x;
    const int lane = tid & 31;
    const int w    = tid >> 5;
    const int r0   = lane >> 2;
    const int cp2  = (lane & 3) * 2;
    const int row_base = blockIdx.x * MROWS;

    // ldmatrix per-thread byte offsets
    const uint32_t aoff = (uint32_t)(((lane & 7) + ((lane >> 3) & 1) * 8) * ASTRIDE
                                     + (lane >> 4) * 16);
    const uint32_t boff = (uint32_t)((lane & 15) * ASTRIDE + w * 64);

    // prime the cp.async pipeline: mat0 chunk0 -> buf0
    cp_chunk(0, 0, 0, sb, tid);

    // biases for this thread's fixed columns
    float b1v[4][2], b2v[4][2];
    #pragma unroll
    for (int nt = 0; nt < 4; nt++) {
        int col = w * 32 + nt * 8 + cp2;
        b1v[nt][0] = b1[col];     b1v[nt][1] = b1[col + 1];
        b2v[nt][0] = b2[col];     b2v[nt][1] = b2[col + 1];
    }

    float c[2][4][4], xv[2][4][4], kc[2][4][4];

    // init: x0 -> registers + A tile (fp16) + trajectory frame 0
    #pragma unroll
    for (int mt = 0; mt < 2; mt++)
        #pragma unroll
        for (int nt = 0; nt < 4; nt++) {
            int col = w * 32 + nt * 8 + cp2;
            #pragma unroll
            for (int rh = 0; rh < 2; rh++) {
                int row = mt * 16 + r0 + rh * 8;
                long long g = (long long)(row_base + row) * DIM + col;
                float v0 = x0[g], v1 = x0[g + 1];
                xv[mt][nt][rh * 2]     = v0;
                xv[mt][nt][rh * 2 + 1] = v1;
                traj[g] = v0; traj[g + 1] = v1;
                hstore(sb + (uint32_t)(row * ASTRIDE + col * 2), v0, v1);
            }
            #pragma unroll
            for (int e = 0; e < 4; e++) c[mt][nt][e] = b1v[nt][e & 1];
        }

    if (times != nullptr && blockIdx.x == 0) {
        float t0 = tspan[0];
        for (int i = tid; i <= NSTEPS; i += NTHREADS)
            times[i] = t0 + 0.01f * (float)i;
    }

    const float halfdt = 0.005f;
    const float dt     = 0.01f;
    const float sixth  = (float)(0.01 / 6.0);
    const long long frame = (long long)BROWS * DIM;

    #pragma unroll 1
    for (int step = 0; step < NSTEPS; step++) {
        #pragma unroll 1
        for (int s = 0; s < 4; s++) {
            // -------- one vf eval: 8 k64 chunks (4 x W1, 4 x W2) --------
            #pragma unroll 1
            for (int t = 0; t < 8; t++) {
                int imat = (t < 3) ? 0 : (t < 7) ? 1 : 0;
                int ic   = (t < 3) ? t + 1 : (t < 7) ? t - 3 : 0;
                cp_chunk(imat, ic, (t + 1) & 1, sb, tid);
                asm volatile("cp.async.wait_group 1;\n" ::: "memory");
                __syncthreads();                 // chunk resident, A visible
                compute_chunk(c, sb, t & 1, aoff,
                              (uint32_t)(t & 3) * 128u, boff);
                __syncthreads();                 // done with buf + A reads

                if (t == 3) {                    // epi1: h = tanh(D) -> A
                    #pragma unroll
                    for (int mt = 0; mt < 2; mt++)
                        #pragma unroll
                        for (int nt = 0; nt < 4; nt++) {
                            int col = w * 32 + nt * 8 + cp2;
                            #pragma unroll
                            for (int rh = 0; rh < 2; rh++) {
                                int row = mt * 16 + r0 + rh * 8;
                                float v0 = tanhf(c[mt][nt][rh * 2]);
                                float v1 = tanhf(c[mt][nt][rh * 2 + 1]);
                                hstore(sb + (uint32_t)(row * ASTRIDE + col * 2),
                                       v0, v1);
                            }
                            #pragma unroll
                            for (int e = 0; e < 4; e++)
                                c[mt][nt][e] = b2v[nt][e & 1];
                        }
                }
            }

            // -------- epi2: k ready in c; RK4 combine; next A --------
            #pragma unroll
            for (int mt = 0; mt < 2; mt++)
                #pragma unroll
                for (int nt = 0; nt < 4; nt++) {
                    int col = w * 32 + nt * 8 + cp2;
                    #pragma unroll
                    for (int rh = 0; rh < 2; rh++) {
                        int row = mt * 16 + r0 + rh * 8;
                        float v[2];
                        #pragma unroll
                        for (int j = 0; j < 2; j++) {
                            int e = rh * 2 + j;
                            float k = c[mt][nt][e];
                            float x = xv[mt][nt][e];
                            if (s == 0) {
                                kc[mt][nt][e] = k;
                                v[j] = x + halfdt * k;
                            } else if (s == 1) {
                                kc[mt][nt][e] += 2.0f * k;
                                v[j] = x + halfdt * k;
                            } else if (s == 2) {
                                kc[mt][nt][e] += 2.0f * k;
                                v[j] = x + dt * k;
                            } else {
                                float xn = x + sixth * (kc[mt][nt][e] + k);
                                xv[mt][nt][e] = xn;
                                v[j] = xn;
                            }
                        }
                        hstore(sb + (uint32_t)(row * ASTRIDE + col * 2),
                               v[0], v[1]);
                        if (s == 3) {
                            long long g = (long long)(step + 1) * frame
                                        + (long long)(row_base + row) * DIM + col;
                            traj[g]     = v[0];
                            traj[g + 1] = v[1];
                        }
                    }
                    #pragma unroll
                    for (int e = 0; e < 4; e++)
                        c[mt][nt][e] = b1v[nt][e & 1];
                }
            // next chunk's pre-compute __syncthreads orders these A writes
        }
    }
}

extern "C" void kernel_launch(void* const* d_in, const int* in_sizes, int n_in,
                              void* d_out, int out_size)
{
    const float* x0    = (const float*)d_in[0];
    const float* tspan = (const float*)d_in[1];
    const float* W1    = (const float*)d_in[2];
    const float* b1    = (const float*)d_in[3];
    const float* W2    = (const float*)d_in[4];
    const float* b2    = (const float*)d_in[5];

    float* out = (float*)d_out;
    const long long traj_elems = (long long)(NSTEPS + 1) * BROWS * DIM;
    float* times = nullptr;
    float* traj  = out;
    if ((long long)out_size >= traj_elems + (NSTEPS + 1)) {
        times = out;
        traj  = out + (NSTEPS + 1);
    }

    repack_kernel<<<512, 256>>>(W1, W2);

    cudaFuncSetAttribute(ode_tc_kernel,
                         cudaFuncAttributeMaxDynamicSharedMemorySize, SMEM_BYTES);
    ode_tc_kernel<<<NCTAS, NTHREADS, SMEM_BYTES>>>(x0, tspan, b1, b2, times, traj);
}

// round 12
// speedup vs baseline: 1.5987x; 1.0926x over previous
#include <cuda_runtime.h>
#include <cuda_fp16.h>
#include <cstdint>

// Neural ODE RK4 on tensor cores via mma.sync (sm_100-safe).
// B=4096, D=H=256, 100 RK4 steps. dx/dt = tanh(x@W1+b1)@W2 + b2.
// fp16 2-term split: D = x_f16 * Wh + x_f16 * Wl (W hi/lo exact to 2^-22).
//
// R12 vs R11 (4028us): overhead reduction, numerics unchanged.
//  - TRIPLE-buffered k64 W chunks -> post-compute __syncthreads removed
//    (safety: cp(q+1) targets the buffer last read at compute(q-2); the
//    pre-compute barrier of iteration q-1 already ordered that chipwide).
//    Barriers: 16 -> 10 per vf eval.
//  - B hi/lo ldsm pairs merged into ldmatrix.x4.trans (lanes 16-31 load the
//    second n8 block): 10 -> 6 ldsm per k16 slice.
//
// 128 persistent CTAs x 32 rows; 8 warps; warp w owns N[w*32..) slab.
// A (x / tanh) single fp16 in smem (528B-padded rows).
//
// Output = flattened tuple (times[101], traj[101,4096,256]); traj starts at
// byte offset 404 -> scalar 4B global stores for trajectory.

#define NSTEPS   100
#define BROWS    4096
#define DIM      256
#define MROWS    32
#define NCTAS    128
#define NTHREADS 256

#define ASTRIDE  528                 // bytes per padded 256-fp16 row
#define PART_EL  16896               // 64 * 264 fp16 elements per k64 part
#define PARTB    (64 * ASTRIDE)      // 33792 B
#define CHUNKB   (2 * PARTB)         // hi+lo, 67584 B
#define W_OFF    16896               // A = 32 rows * 528 B (single fp16)
#define SMEM_BYTES (W_OFF + 3 * CHUNKB)   // 219648

__device__ __align__(16) __half g_Wp[2 * 4 * 2 * PART_EL]; // [mat][chunk][part]

// ---------------- helpers ----------------
__device__ __forceinline__ uint32_t smem_u32(const void* p) {
    uint32_t a;
    asm("{ .reg .u64 t; cvta.to.shared.u64 t, %1; cvt.u32.u64 %0, t; }"
        : "=r"(a) : "l"(p));
    return a;
}
__device__ __forceinline__ void ldsm_x4(uint32_t r[4], uint32_t a) {
    asm volatile("ldmatrix.sync.aligned.m8n8.x4.shared.b16 {%0,%1,%2,%3}, [%4];"
                 : "=r"(r[0]), "=r"(r[1]), "=r"(r[2]), "=r"(r[3]) : "r"(a));
}
// x4 TRANS: lanes 0-15 -> k-rows of n8 block p, lanes 16-31 -> k-rows of
// block p+1 (address adds (lane>>4)*16). r0,r1 = fragment(block p),
// r2,r3 = fragment(block p+1).
__device__ __forceinline__ void ldsm_x4t(uint32_t r[4], uint32_t a) {
    asm volatile("ldmatrix.sync.aligned.m8n8.x4.trans.shared.b16 {%0,%1,%2,%3}, [%4];"
                 : "=r"(r[0]), "=r"(r[1]), "=r"(r[2]), "=r"(r[3]) : "r"(a));
}
__device__ __forceinline__ void mma16816(float c[4], const uint32_t a[4],
                                         const uint32_t b[2]) {
    asm volatile("mma.sync.aligned.m16n8k16.row.col.f32.f16.f16.f32 "
                 "{%0,%1,%2,%3}, {%4,%5,%6,%7}, {%8,%9}, {%0,%1,%2,%3};"
                 : "+f"(c[0]), "+f"(c[1]), "+f"(c[2]), "+f"(c[3])
                 : "r"(a[0]), "r"(a[1]), "r"(a[2]), "r"(a[3]),
                   "r"(b[0]), "r"(b[1]));
}
// round (va, vb) to fp16 pair and store as one b32 into the A tile
__device__ __forceinline__ void hstore(uint32_t addr, float va, float vb) {
    __half2 h = __floats2half2_rn(va, vb);
    uint32_t u = *reinterpret_cast<uint32_t*>(&h);
    asm volatile("st.shared.b32 [%0], %1;" :: "r"(addr), "r"(u) : "memory");
}

// ---------------- repack: W[k][n] fp32 -> hi/lo fp16, padded rows ----------
__global__ void repack_kernel(const float* __restrict__ W1,
                              const float* __restrict__ W2)
{
    int t = blockIdx.x * blockDim.x + threadIdx.x;
    if (t >= 2 * DIM * DIM) return;
    int mat = t >> 16;
    int k   = (t >> 8) & 255;
    int n   = t & 255;
    float w = (mat ? W2 : W1)[k * DIM + n];
    __half h = __float2half_rn(w);
    __half l = __float2half_rn(w - __half2float(h));
    int chunk = k >> 6;
    int idx = (mat * 4 + chunk) * 2 * PART_EL + (k & 63) * 264 + n;
    g_Wp[idx]           = h;
    g_Wp[idx + PART_EL] = l;
}

// ---------------- main kernel ----------------
extern __shared__ char smem_raw[];

__device__ __forceinline__ void cp_chunk(int mat, int c, int buf,
                                         uint32_t sb, int tid)
{
    uint32_t dst = sb + W_OFF + (uint32_t)buf * CHUNKB;
    const char* src = reinterpret_cast<const char*>(g_Wp)
                    + (size_t)(mat * 4 + c) * CHUNKB;
    for (int i = tid; i < CHUNKB / 16; i += NTHREADS) {
        asm volatile("cp.async.cg.shared.global [%0], [%1], 16;\n"
                     :: "r"(dst + (uint32_t)i * 16u), "l"(src + (size_t)i * 16));
    }
    asm volatile("cp.async.commit_group;\n" ::: "memory");
}

// one k64 chunk of the M32 x N32 (per-warp) GEMM, 2-term fp16 split.
// akoff = byte offset of this chunk's k64 slice within the A row (kchunk*128).
__device__ __forceinline__ void compute_chunk(float c[2][4][4], uint32_t sb,
                                              int buf, uint32_t aoff,
                                              uint32_t akoff, uint32_t boff4)
{
    uint32_t wb = sb + W_OFF + (uint32_t)buf * CHUNKB;
    #pragma unroll
    for (int ks = 0; ks < 4; ks++) {
        uint32_t ab = sb + aoff + akoff + (uint32_t)ks * 32u;
        uint32_t a0[4], a1[4];
        ldsm_x4(a0, ab);
        ldsm_x4(a1, ab + 16u * ASTRIDE);

        uint32_t bb = wb + boff4 + (uint32_t)ks * 16u * ASTRIDE;
        uint32_t bh[4][2], bl[4][2];
        #pragma unroll
        for (int p = 0; p < 2; p++) {                 // n8 block pairs
            uint32_t q[4];
            ldsm_x4t(q, bb + (uint32_t)p * 32u);
            bh[2*p][0] = q[0]; bh[2*p][1] = q[1];
            bh[2*p+1][0] = q[2]; bh[2*p+1][1] = q[3];
            ldsm_x4t(q, bb + PARTB + (uint32_t)p * 32u);
            bl[2*p][0] = q[0]; bl[2*p][1] = q[1];
            bl[2*p+1][0] = q[2]; bl[2*p+1][1] = q[3];
        }
        // term 1: x * Wh  (term-major: 8 distinct accumulators in a row)
        #pragma unroll
        for (int nt = 0; nt < 4; nt++) {
            mma16816(c[0][nt], a0, bh[nt]);
            mma16816(c[1][nt], a1, bh[nt]);
        }
        // term 2: x * Wl
        #pragma unroll
        for (int nt = 0; nt < 4; nt++) {
            mma16816(c[0][nt], a0, bl[nt]);
            mma16816(c[1][nt], a1, bl[nt]);
        }
    }
}

__global__ void __launch_bounds__(NTHREADS, 1)
ode_tc_kernel(const float* __restrict__ x0, const float* __restrict__ tspan,
              const float* __restrict__ b1, const float* __restrict__ b2,
              float* __restrict__ times, float* __restrict__ traj)
{
    uint32_t sb = smem_u32(smem_raw);
    const int tid  = threadIdx.x;
    const int lane = tid & 31;
    const int w    = tid >> 5;
    const int r0   = lane >> 2;
    const int cp2  = (lane & 3) * 2;
    const int row_base = blockIdx.x * MROWS;

    // ldmatrix per-thread byte offsets
    const uint32_t aoff  = (uint32_t)(((lane & 7) + ((lane >> 3) & 1) * 8) * ASTRIDE
                                      + (lane >> 4) * 16);
    const uint32_t boff4 = (uint32_t)((lane & 15) * ASTRIDE
                                      + ((lane >> 4) & 1) * 16 + w * 64);

    // prime the cp.async pipeline: mat0 chunk0 -> buf0
    cp_chunk(0, 0, 0, sb, tid);

    // biases for this thread's fixed columns
    float b1v[4][2], b2v[4][2];
    #pragma unroll
    for (int nt = 0; nt < 4; nt++) {
        int col = w * 32 + nt * 8 + cp2;
        b1v[nt][0] = b1[col];     b1v[nt][1] = b1[col + 1];
        b2v[nt][0] = b2[col];     b2v[nt][1] = b2[col + 1];
    }

    float c[2][4][4], xv[2][4][4], kc[2][4][4];

    // init: x0 -> registers + A tile (fp16) + trajectory frame 0
    #pragma unroll
    for (int mt = 0; mt < 2; mt++)
        #pragma unroll
        for (int nt = 0; nt < 4; nt++) {
            int col = w * 32 + nt * 8 + cp2;
            #pragma unroll
            for (int rh = 0; rh < 2; rh++) {
                int row = mt * 16 + r0 + rh * 8;
                long long g = (long long)(row_base + row) * DIM + col;
                float v0 = x0[g], v1 = x0[g + 1];
                xv[mt][nt][rh * 2]     = v0;
                xv[mt][nt][rh * 2 + 1] = v1;
                traj[g] = v0; traj[g + 1] = v1;
                hstore(sb + (uint32_t)(row * ASTRIDE + col * 2), v0, v1);
            }
            #pragma unroll
            for (int e = 0; e < 4; e++) c[mt][nt][e] = b1v[nt][e & 1];
        }

    if (times != nullptr && blockIdx.x == 0) {
        float t0 = tspan[0];
        for (int i = tid; i <= NSTEPS; i += NTHREADS)
            times[i] = t0 + 0.01f * (float)i;
    }

    const float halfdt = 0.005f;
    const float dt     = 0.01f;
    const float sixth  = (float)(0.01 / 6.0);
    const long long frame = (long long)BROWS * DIM;

    int cur = 0;    // smem buffer holding the chunk about to be computed

    #pragma unroll 1
    for (int step = 0; step < NSTEPS; step++) {
        #pragma unroll 1
        for (int s = 0; s < 4; s++) {
            // -------- one vf eval: 8 k64 chunks (4 x W1, 4 x W2) --------
            #pragma unroll 1
            for (int t = 0; t < 8; t++) {
                int imat = (t < 3) ? 0 : (t < 7) ? 1 : 0;
                int ic   = (t < 3) ? t + 1 : (t < 7) ? t - 3 : 0;
                int nb = cur + 1; if (nb == 3) nb = 0;
                cp_chunk(imat, ic, nb, sb, tid);
                asm volatile("cp.async.wait_group 1;\n" ::: "memory");
                __syncthreads();   // chunk 'cur' visible to all warps; prior
                                   // compute (t-1) finished chipwide; epi
                                   // A-writes visible
                compute_chunk(c, sb, cur, aoff,
                              (uint32_t)(t & 3) * 128u, boff4);
                cur = nb;

                if (t == 3) {      // all warps done reading A (sync), then
                    __syncthreads();            // overwrite A with tanh(h)
                    #pragma unroll
                    for (int mt = 0; mt < 2; mt++)
                        #pragma unroll
                        for (int nt = 0; nt < 4; nt++) {
                            int col = w * 32 + nt * 8 + cp2;
                            #pragma unroll
                            for (int rh = 0; rh < 2; rh++) {
                                int row = mt * 16 + r0 + rh * 8;
                                float v0 = tanhf(c[mt][nt][rh * 2]);
                                float v1 = tanhf(c[mt][nt][rh * 2 + 1]);
                                hstore(sb + (uint32_t)(row * ASTRIDE + col * 2),
                                       v0, v1);
                            }
                            #pragma unroll
                            for (int e = 0; e < 4; e++)
                                c[mt][nt][e] = b2v[nt][e & 1];
                        }
                }
            }

            // -------- epi2: all warps done reading A, then RK4 combine ----
            __syncthreads();
            #pragma unroll
            for (int mt = 0; mt < 2; mt++)
                #pragma unroll
                for (int nt = 0; nt < 4; nt++) {
                    int col = w * 32 + nt * 8 + cp2;
                    #pragma unroll
                    for (int rh = 0; rh < 2; rh++) {
                        int row = mt * 16 + r0 + rh * 8;
                        float v[2];
                        #pragma unroll
                        for (int j = 0; j < 2; j++) {
                            int e = rh * 2 + j;
                            float k = c[mt][nt][e];
                            float x = xv[mt][nt][e];
                            if (s == 0) {
                                kc[mt][nt][e] = k;
                                v[j] = x + halfdt * k;
                            } else if (s == 1) {
                                kc[mt][nt][e] += 2.0f * k;
                                v[j] = x + halfdt * k;
                            } else if (s == 2) {
                                kc[mt][nt][e] += 2.0f * k;
                                v[j] = x + dt * k;
                            } else {
                                float xn = x + sixth * (kc[mt][nt][e] + k);
                                xv[mt][nt][e] = xn;
                                v[j] = xn;
                            }
                        }
                        hstore(sb + (uint32_t)(row * ASTRIDE + col * 2),
                               v[0], v[1]);
                        if (s == 3) {
                            long long g = (long long)(step + 1) * frame
                                        + (long long)(row_base + row) * DIM + col;
                            traj[g]     = v[0];
                            traj[g + 1] = v[1];
                        }
                    }
                    #pragma unroll
                    for (int e = 0; e < 4; e++)
                        c[mt][nt][e] = b1v[nt][e & 1];
                }
            // next chunk's pre-compute __syncthreads orders these A writes
        }
    }
}

extern "C" void kernel_launch(void* const* d_in, const int* in_sizes, int n_in,
                              void* d_out, int out_size)
{
    const float* x0    = (const float*)d_in[0];
    const float* tspan = (const float*)d_in[1];
    const float* W1    = (const float*)d_in[2];
    const float* b1    = (const float*)d_in[3];
    const float* W2    = (const float*)d_in[4];
    const float* b2    = (const float*)d_in[5];

    float* out = (float*)d_out;
    const long long traj_elems = (long long)(NSTEPS + 1) * BROWS * DIM;
    float* times = nullptr;
    float* traj  = out;
    if ((long long)out_size >= traj_elems + (NSTEPS + 1)) {
        times = out;
        traj  = out + (NSTEPS + 1);
    }

    repack_kernel<<<512, 256>>>(W1, W2);

    cudaFuncSetAttribute(ode_tc_kernel,
                         cudaFuncAttributeMaxDynamicSharedMemorySize, SMEM_BYTES);
    ode_tc_kernel<<<NCTAS, NTHREADS, SMEM_BYTES>>>(x0, tspan, b1, b2, times, traj);
}

// round 13
// speedup vs baseline: 2.4031x; 1.5032x over previous
#include <cuda_runtime.h>
#include <cuda_fp16.h>
#include <cstdint>

// Neural ODE RK4 on tensor cores via mma.sync (sm_100-safe).
// B=4096, D=H=256, 100 RK4 steps. dx/dt = tanh(x@W1+b1)@W2 + b2.
//
// R13: SINGLE-term fp16 (D = x_f16 * W_f16). W rounding is a systematic
// 2^-11-class perturbation; measured 2-term run (x-error only) gave 9.2e-6,
// 108x under the 1e-3 budget, so we spend error budget for a 2x MMA cut.
// Also: k128 W chunks (fewer barriers: 10 -> 6 per vf), B-ldsm halved.
//
// 128 persistent CTAs x 32 rows; 8 warps; warp w owns N[w*32..) slab.
// A (x / tanh) single fp16 in smem (528B-padded rows). W streamed as
// TRIPLE-buffered k128 chunks via cp.async (post-compute barrier elided:
// cp(q+1) targets the buffer last read at compute(q-2), ordered by the
// pre-compute barrier of iteration q-1).
//
// Output = flattened tuple (times[101], traj[101,4096,256]); traj starts at
// byte offset 404 -> scalar 4B global stores for trajectory.

#define NSTEPS   100
#define BROWS    4096
#define DIM      256
#define MROWS    32
#define NCTAS    128
#define NTHREADS 256

#define ASTRIDE  528                 // bytes per padded 256-fp16 row
#define CHUNK_EL (128 * 264)         // k128 chunk, fp16 elements
#define CHUNKB   (128 * ASTRIDE)     // 67584 B
#define W_OFF    16896               // A = 32 rows * 528 B (single fp16)
#define SMEM_BYTES (W_OFF + 3 * CHUNKB)   // 219648

__device__ __align__(16) __half g_Wp[2 * 2 * CHUNK_EL]; // [mat][chunk k128]

// ---------------- helpers ----------------
__device__ __forceinline__ uint32_t smem_u32(const void* p) {
    uint32_t a;
    asm("{ .reg .u64 t; cvta.to.shared.u64 t, %1; cvt.u32.u64 %0, t; }"
        : "=r"(a) : "l"(p));
    return a;
}
__device__ __forceinline__ void ldsm_x4(uint32_t r[4], uint32_t a) {
    asm volatile("ldmatrix.sync.aligned.m8n8.x4.shared.b16 {%0,%1,%2,%3}, [%4];"
                 : "=r"(r[0]), "=r"(r[1]), "=r"(r[2]), "=r"(r[3]) : "r"(a));
}
// x4 TRANS: lanes 0-15 -> k-rows of n8 block p, lanes 16-31 -> block p+1.
__device__ __forceinline__ void ldsm_x4t(uint32_t r[4], uint32_t a) {
    asm volatile("ldmatrix.sync.aligned.m8n8.x4.trans.shared.b16 {%0,%1,%2,%3}, [%4];"
                 : "=r"(r[0]), "=r"(r[1]), "=r"(r[2]), "=r"(r[3]) : "r"(a));
}
__device__ __forceinline__ void mma16816(float c[4], const uint32_t a[4],
                                         const uint32_t b[2]) {
    asm volatile("mma.sync.aligned.m16n8k16.row.col.f32.f16.f16.f32 "
                 "{%0,%1,%2,%3}, {%4,%5,%6,%7}, {%8,%9}, {%0,%1,%2,%3};"
                 : "+f"(c[0]), "+f"(c[1]), "+f"(c[2]), "+f"(c[3])
                 : "r"(a[0]), "r"(a[1]), "r"(a[2]), "r"(a[3]),
                   "r"(b[0]), "r"(b[1]));
}
// round (va, vb) to fp16 pair and store as one b32 into the A tile
__device__ __forceinline__ void hstore(uint32_t addr, float va, float vb) {
    __half2 h = __floats2half2_rn(va, vb);
    uint32_t u = *reinterpret_cast<uint32_t*>(&h);
    asm volatile("st.shared.b32 [%0], %1;" :: "r"(addr), "r"(u) : "memory");
}

// ---------------- repack: W[k][n] fp32 -> fp16, padded rows ----------
__global__ void repack_kernel(const float* __restrict__ W1,
                              const float* __restrict__ W2)
{
    int t = blockIdx.x * blockDim.x + threadIdx.x;
    if (t >= 2 * DIM * DIM) return;
    int mat = t >> 16;
    int k   = (t >> 8) & 255;
    int n   = t & 255;
    float w = (mat ? W2 : W1)[k * DIM + n];
    int chunk = k >> 7;
    g_Wp[(mat * 2 + chunk) * CHUNK_EL + (k & 127) * 264 + n] = __float2half_rn(w);
}

// ---------------- main kernel ----------------
extern __shared__ char smem_raw[];

__device__ __forceinline__ void cp_chunk(int mat, int c, int buf,
                                         uint32_t sb, int tid)
{
    uint32_t dst = sb + W_OFF + (uint32_t)buf * CHUNKB;
    const char* src = reinterpret_cast<const char*>(g_Wp)
                    + (size_t)(mat * 2 + c) * CHUNKB;
    for (int i = tid; i < CHUNKB / 16; i += NTHREADS) {
        asm volatile("cp.async.cg.shared.global [%0], [%1], 16;\n"
                     :: "r"(dst + (uint32_t)i * 16u), "l"(src + (size_t)i * 16));
    }
    asm volatile("cp.async.commit_group;\n" ::: "memory");
}

// one k128 chunk of the M32 x N32 (per-warp) GEMM, single-term fp16.
// akoff = byte offset of this chunk's k128 slice within the A row.
__device__ __forceinline__ void compute_chunk(float c[2][4][4], uint32_t sb,
                                              int buf, uint32_t aoff,
                                              uint32_t akoff, uint32_t boff4)
{
    uint32_t wb = sb + W_OFF + (uint32_t)buf * CHUNKB;
    #pragma unroll
    for (int ks = 0; ks < 8; ks++) {
        uint32_t ab = sb + aoff + akoff + (uint32_t)ks * 32u;
        uint32_t a0[4], a1[4];
        ldsm_x4(a0, ab);
        ldsm_x4(a1, ab + 16u * ASTRIDE);

        uint32_t bb = wb + boff4 + (uint32_t)ks * 16u * ASTRIDE;
        uint32_t bh[4][2];
        #pragma unroll
        for (int p = 0; p < 2; p++) {                 // n8 block pairs
            uint32_t q[4];
            ldsm_x4t(q, bb + (uint32_t)p * 32u);
            bh[2*p][0] = q[0];   bh[2*p][1] = q[1];
            bh[2*p+1][0] = q[2]; bh[2*p+1][1] = q[3];
        }
        #pragma unroll
        for (int nt = 0; nt < 4; nt++) {
            mma16816(c[0][nt], a0, bh[nt]);
            mma16816(c[1][nt], a1, bh[nt]);
        }
    }
}

__global__ void __launch_bounds__(NTHREADS, 1)
ode_tc_kernel(const float* __restrict__ x0, const float* __restrict__ tspan,
              const float* __restrict__ b1, const float* __restrict__ b2,
              float* __restrict__ times, float* __restrict__ traj)
{
    uint32_t sb = smem_u32(smem_raw);
    const int tid  = threadIdx.x;
    const int lane = tid & 31;
    const int w    = tid >> 5;
    const int r0   = lane >> 2;
    const int cp2  = (lane & 3) * 2;
    const int row_base = blockIdx.x * MROWS;

    // ldmatrix per-thread byte offsets
    const uint32_t aoff  = (uint32_t)(((lane & 7) + ((lane >> 3) & 1) * 8) * ASTRIDE
                                      + (lane >> 4) * 16);
    const uint32_t boff4 = (uint32_t)((lane & 15) * ASTRIDE
                                      + ((lane >> 4) & 1) * 16 + w * 64);

    // prime the cp.async pipeline: mat0 chunk0 -> buf0
    cp_chunk(0, 0, 0, sb, tid);

    // biases for this thread's fixed columns
    float b1v[4][2], b2v[4][2];
    #pragma unroll
    for (int nt = 0; nt < 4; nt++) {
        int col = w * 32 + nt * 8 + cp2;
        b1v[nt][0] = b1[col];     b1v[nt][1] = b1[col + 1];
        b2v[nt][0] = b2[col];     b2v[nt][1] = b2[col + 1];
    }

    float c[2][4][4], xv[2][4][4], kc[2][4][4];

    // init: x0 -> registers + A tile (fp16) + trajectory frame 0
    #pragma unroll
    for (int mt = 0; mt < 2; mt++)
        #pragma unroll
        for (int nt = 0; nt < 4; nt++) {
            int col = w * 32 + nt * 8 + cp2;
            #pragma unroll
            for (int rh = 0; rh < 2; rh++) {
                int row = mt * 16 + r0 + rh * 8;
                long long g = (long long)(row_base + row) * DIM + col;
                float v0 = x0[g], v1 = x0[g + 1];
                xv[mt][nt][rh * 2]     = v0;
                xv[mt][nt][rh * 2 + 1] = v1;
                traj[g] = v0; traj[g + 1] = v1;
                hstore(sb + (uint32_t)(row * ASTRIDE + col * 2), v0, v1);
            }
            #pragma unroll
            for (int e = 0; e < 4; e++) c[mt][nt][e] = b1v[nt][e & 1];
        }

    if (times != nullptr && blockIdx.x == 0) {
        float t0 = tspan[0];
        for (int i = tid; i <= NSTEPS; i += NTHREADS)
            times[i] = t0 + 0.01f * (float)i;
    }

    const float halfdt = 0.005f;
    const float dt     = 0.01f;
    const float sixth  = (float)(0.01 / 6.0);
    const long long frame = (long long)BROWS * DIM;

    int cur = 0;    // smem buffer holding the chunk about to be computed

    #pragma unroll 1
    for (int step = 0; step < NSTEPS; step++) {
        #pragma unroll 1
        for (int s = 0; s < 4; s++) {
            // -------- one vf eval: 4 k128 chunks (2 x W1, 2 x W2) --------
            #pragma unroll 1
            for (int t = 0; t < 4; t++) {
                int next = (t + 1) & 3;
                int nb = cur + 1; if (nb == 3) nb = 0;
                cp_chunk(next >> 1, next & 1, nb, sb, tid);
                asm volatile("cp.async.wait_group 1;\n" ::: "memory");
                __syncthreads();   // chunk 'cur' visible; prior compute done
                                   // chipwide; epi A-writes visible
                compute_chunk(c, sb, cur, aoff,
                              (uint32_t)(t & 1) * 256u, boff4);
                cur = nb;

                if (t == 1) {      // all warps done reading A (sync), then
                    __syncthreads();            // overwrite A with tanh(h)
                    #pragma unroll
                    for (int mt = 0; mt < 2; mt++)
                        #pragma unroll
                        for (int nt = 0; nt < 4; nt++) {
                            int col = w * 32 + nt * 8 + cp2;
                            #pragma unroll
                            for (int rh = 0; rh < 2; rh++) {
                                int row = mt * 16 + r0 + rh * 8;
                                float v0 = tanhf(c[mt][nt][rh * 2]);
                                float v1 = tanhf(c[mt][nt][rh * 2 + 1]);
                                hstore(sb + (uint32_t)(row * ASTRIDE + col * 2),
                                       v0, v1);
                            }
                            #pragma unroll
                            for (int e = 0; e < 4; e++)
                                c[mt][nt][e] = b2v[nt][e & 1];
                        }
                }
            }

            // -------- epi2: all warps done reading A, then RK4 combine ----
            __syncthreads();
            #pragma unroll
            for (int mt = 0; mt < 2; mt++)
                #pragma unroll
                for (int nt = 0; nt < 4; nt++) {
                    int col = w * 32 + nt * 8 + cp2;
                    #pragma unroll
                    for (int rh = 0; rh < 2; rh++) {
                        int row = mt * 16 + r0 + rh * 8;
                        float v[2];
                        #pragma unroll
                        for (int j = 0; j < 2; j++) {
                            int e = rh * 2 + j;
                            float k = c[mt][nt][e];
                            float x = xv[mt][nt][e];
                            if (s == 0) {
                                kc[mt][nt][e] = k;
                                v[j] = x + halfdt * k;
                            } else if (s == 1) {
                                kc[mt][nt][e] += 2.0f * k;
                                v[j] = x + halfdt * k;
                            } else if (s == 2) {
                                kc[mt][nt][e] += 2.0f * k;
                                v[j] = x + dt * k;
                            } else {
                                float xn = x + sixth * (kc[mt][nt][e] + k);
                                xv[mt][nt][e] = xn;
                                v[j] = xn;
                            }
                        }
                        hstore(sb + (uint32_t)(row * ASTRIDE + col * 2),
                               v[0], v[1]);
                        if (s == 3) {
                            long long g = (long long)(step + 1) * frame
                                        + (long long)(row_base + row) * DIM + col;
                            traj[g]     = v[0];
                            traj[g + 1] = v[1];
                        }
                    }
                    #pragma unroll
                    for (int e = 0; e < 4; e++)
                        c[mt][nt][e] = b1v[nt][e & 1];
                }
            // next chunk's pre-compute __syncthreads orders these A writes
        }
    }
}

extern "C" void kernel_launch(void* const* d_in, const int* in_sizes, int n_in,
                              void* d_out, int out_size)
{
    const float* x0    = (const float*)d_in[0];
    const float* tspan = (const float*)d_in[1];
    const float* W1    = (const float*)d_in[2];
    const float* b1    = (const float*)d_in[3];
    const float* W2    = (const float*)d_in[4];
    const float* b2    = (const float*)d_in[5];

    float* out = (float*)d_out;
    const long long traj_elems = (long long)(NSTEPS + 1) * BROWS * DIM;
    float* times = nullptr;
    float* traj  = out;
    if ((long long)out_size >= traj_elems + (NSTEPS + 1)) {
        times = out;
        traj  = out + (NSTEPS + 1);
    }

    repack_kernel<<<512, 256>>>(W1, W2);

    cudaFuncSetAttribute(ode_tc_kernel,
                         cudaFuncAttributeMaxDynamicSharedMemorySize, SMEM_BYTES);
    ode_tc_kernel<<<NCTAS, NTHREADS, SMEM_BYTES>>>(x0, tspan, b1, b2, times, traj);
}

// round 14
// speedup vs baseline: 2.9573x; 1.2306x over previous
#include <cuda_runtime.h>
#include <cuda_fp16.h>
#include <cstdint>

// Neural ODE RK4 on tensor cores via mma.sync (sm_100-safe).
// B=4096, D=H=256, 100 RK4 steps. dx/dt = tanh(x@W1+b1)@W2 + b2.
// Single-term fp16 GEMMs (D = x_f16 * W_f16), fp32 accum (rel_err 1.09e-4).
//
// R14 vs R13 (2453us): copy/overhead reduction, numerics bit-identical.
//  - W chunks loaded with ONE cp.async.bulk (+mbarrier complete_tx) issued by
//    thread 0, replacing 4224 per-thread cp.async per chunk (ALU/issue storm).
//  - W readiness = per-buffer mbarrier parity wait (no warp coupling);
//    __syncthreads only where A has RAW/WAR hazards: 6 -> 4 per vf eval.
//    WAR safety on the triple buffer: each bulk targeting buffer b is issued
//    after a syncthreads all warps passed after their last read of b.
//
// 128 persistent CTAs x 32 rows; 8 warps; warp w owns N[w*32..) slab.
// A (x / tanh) single fp16 in smem (528B-padded rows).
//
// Output = flattened tuple (times[101], traj[101,4096,256]); traj starts at
// byte offset 404 -> scalar 4B global stores for trajectory.

#define NSTEPS   100
#define BROWS    4096
#define DIM      256
#define MROWS    32
#define NCTAS    128
#define NTHREADS 256

#define ASTRIDE  528                 // bytes per padded 256-fp16 row
#define CHUNK_EL (128 * 264)         // k128 chunk, fp16 elements
#define CHUNKB   (128 * ASTRIDE)     // 67584 B
#define MBAR_OFF 0                   // 3 x 8B mbarriers
#define A_OFF    64
#define W_OFF    (A_OFF + 16896)     // A = 32 rows * 528 B
#define SMEM_BYTES (W_OFF + 3 * CHUNKB)   // 219712

__device__ __align__(16) __half g_Wp[2 * 2 * CHUNK_EL]; // [mat][chunk k128]

// ---------------- helpers ----------------
__device__ __forceinline__ uint32_t smem_u32(const void* p) {
    uint32_t a;
    asm("{ .reg .u64 t; cvta.to.shared.u64 t, %1; cvt.u32.u64 %0, t; }"
        : "=r"(a) : "l"(p));
    return a;
}
__device__ __forceinline__ void ldsm_x4(uint32_t r[4], uint32_t a) {
    asm volatile("ldmatrix.sync.aligned.m8n8.x4.shared.b16 {%0,%1,%2,%3}, [%4];"
                 : "=r"(r[0]), "=r"(r[1]), "=r"(r[2]), "=r"(r[3]) : "r"(a));
}
__device__ __forceinline__ void ldsm_x4t(uint32_t r[4], uint32_t a) {
    asm volatile("ldmatrix.sync.aligned.m8n8.x4.trans.shared.b16 {%0,%1,%2,%3}, [%4];"
                 : "=r"(r[0]), "=r"(r[1]), "=r"(r[2]), "=r"(r[3]) : "r"(a));
}
__device__ __forceinline__ void mma16816(float c[4], const uint32_t a[4],
                                         const uint32_t b[2]) {
    asm volatile("mma.sync.aligned.m16n8k16.row.col.f32.f16.f16.f32 "
                 "{%0,%1,%2,%3}, {%4,%5,%6,%7}, {%8,%9}, {%0,%1,%2,%3};"
                 : "+f"(c[0]), "+f"(c[1]), "+f"(c[2]), "+f"(c[3])
                 : "r"(a[0]), "r"(a[1]), "r"(a[2]), "r"(a[3]),
                   "r"(b[0]), "r"(b[1]));
}
__device__ __forceinline__ void hstore(uint32_t addr, float va, float vb) {
    __half2 h = __floats2half2_rn(va, vb);
    uint32_t u = *reinterpret_cast<uint32_t*>(&h);
    asm volatile("st.shared.b32 [%0], %1;" :: "r"(addr), "r"(u) : "memory");
}
#define MBARRIER_INIT(a, cnt) \
    asm volatile("mbarrier.init.shared.b64 [%0], %1;" :: "r"(a), "r"(cnt) : "memory")
#define MBARRIER_EXPECT_TX(a, bytes) \
    asm volatile("mbarrier.arrive.expect_tx.shared.b64 _, [%0], %1;" \
                 :: "r"(a), "r"(bytes) : "memory")
#define MBARRIER_WAIT_PARITY(mb, prty) do {                                    \
    uint32_t _m = (uint32_t)(mb), _p = (uint32_t)(prty), _d;                   \
    asm volatile("{\n\t.reg .pred p;\n\t"                                      \
        "mbarrier.try_wait.parity.acquire.cta.shared::cta.b64 p, [%1], %2;\n\t"\
        "selp.b32 %0, 1, 0, p;\n\t}" : "=r"(_d) : "r"(_m), "r"(_p) : "memory");\
    if (!_d) {                                                                 \
        asm volatile("{\n\t.reg .pred P1;\n\tWL_%=:\n\t"                       \
            "mbarrier.try_wait.parity.acquire.cta.shared::cta.b64 P1, [%0], %1, 0x989680;\n\t"\
            "@P1 bra.uni WD_%=;\n\tbra.uni WL_%=;\n\tWD_%=:\n\t}"              \
            :: "r"(_m), "r"(_p) : "memory");                                   \
    }                                                                          \
} while (0)

// ---------------- repack: W[k][n] fp32 -> fp16, padded rows ----------
__global__ void repack_kernel(const float* __restrict__ W1,
                              const float* __restrict__ W2)
{
    int t = blockIdx.x * blockDim.x + threadIdx.x;
    if (t >= 2 * DIM * DIM) return;
    int mat = t >> 16;
    int k   = (t >> 8) & 255;
    int n   = t & 255;
    float w = (mat ? W2 : W1)[k * DIM + n];
    int chunk = k >> 7;
    g_Wp[(mat * 2 + chunk) * CHUNK_EL + (k & 127) * 264 + n] = __float2half_rn(w);
}

// ---------------- main kernel ----------------
extern __shared__ char smem_raw[];

// one cp.async.bulk of a full k128 chunk into buffer buf, completing mbar.
__device__ __forceinline__ void bulk_cp(int chunkid, int buf, uint32_t sb)
{
    uint32_t bar = sb + MBAR_OFF + (uint32_t)buf * 8u;
    uint32_t dst = sb + W_OFF + (uint32_t)buf * CHUNKB;
    const char* src = reinterpret_cast<const char*>(g_Wp)
                    + (size_t)chunkid * CHUNKB;
    MBARRIER_EXPECT_TX(bar, (uint32_t)CHUNKB);
    asm volatile("cp.async.bulk.shared::cta.global.mbarrier::complete_tx::bytes "
                 "[%0], [%1], %2, [%3];"
                 :: "r"(dst), "l"(src), "r"((uint32_t)CHUNKB), "r"(bar)
                 : "memory");
}

// one k128 chunk of the M32 x N32 (per-warp) GEMM, single-term fp16.
__device__ __forceinline__ void compute_chunk(float c[2][4][4], uint32_t sb,
                                              int buf, uint32_t aoff,
                                              uint32_t akoff, uint32_t boff4)
{
    uint32_t wb = sb + W_OFF + (uint32_t)buf * CHUNKB;
    #pragma unroll
    for (int ks = 0; ks < 8; ks++) {
        uint32_t ab = sb + A_OFF + aoff + akoff + (uint32_t)ks * 32u;
        uint32_t a0[4], a1[4];
        ldsm_x4(a0, ab);
        ldsm_x4(a1, ab + 16u * ASTRIDE);

        uint32_t bb = wb + boff4 + (uint32_t)ks * 16u * ASTRIDE;
        uint32_t bh[4][2];
        #pragma unroll
        for (int p = 0; p < 2; p++) {                 // n8 block pairs
            uint32_t q[4];
            ldsm_x4t(q, bb + (uint32_t)p * 32u);
            bh[2*p][0] = q[0];   bh[2*p][1] = q[1];
            bh[2*p+1][0] = q[2]; bh[2*p+1][1] = q[3];
        }
        #pragma unroll
        for (int nt = 0; nt < 4; nt++) {
            mma16816(c[0][nt], a0, bh[nt]);
            mma16816(c[1][nt], a1, bh[nt]);
        }
    }
}

__global__ void __launch_bounds__(NTHREADS, 1)
ode_tc_kernel(const float* __restrict__ x0, const float* __restrict__ tspan,
              const float* __restrict__ b1, const float* __restrict__ b2,
              float* __restrict__ times, float* __restrict__ traj)
{
    uint32_t sb = smem_u32(smem_raw);
    const int tid  = threadIdx.x;
    const int lane = tid & 31;
    const int w    = tid >> 5;
    const int r0   = lane >> 2;
    const int cp2  = (lane & 3) * 2;
    const int row_base = blockIdx.x * MROWS;

    // ldmatrix per-thread byte offsets
    const uint32_t aoff  = (uint32_t)(((lane & 7) + ((lane >> 3) & 1) * 8) * ASTRIDE
                                      + (lane >> 4) * 16);
    const uint32_t boff4 = (uint32_t)((lane & 15) * ASTRIDE
                                      + ((lane >> 4) & 1) * 16 + w * 64);

    // mbarrier init, then prime the pipeline: chunk0 -> buf0
    if (tid == 0) {
        MBARRIER_INIT(sb + MBAR_OFF + 0u, 1);
        MBARRIER_INIT(sb + MBAR_OFF + 8u, 1);
        MBARRIER_INIT(sb + MBAR_OFF + 16u, 1);
    }
    __syncthreads();
    if (tid == 0) bulk_cp(0, 0, sb);

    // biases for this thread's fixed columns
    float b1v[4][2], b2v[4][2];
    #pragma unroll
    for (int nt = 0; nt < 4; nt++) {
        int col = w * 32 + nt * 8 + cp2;
        b1v[nt][0] = b1[col];     b1v[nt][1] = b1[col + 1];
        b2v[nt][0] = b2[col];     b2v[nt][1] = b2[col + 1];
    }

    float c[2][4][4], xv[2][4][4], kc[2][4][4];

    // init: x0 -> registers + A tile (fp16) + trajectory frame 0
    #pragma unroll
    for (int mt = 0; mt < 2; mt++)
        #pragma unroll
        for (int nt = 0; nt < 4; nt++) {
            int col = w * 32 + nt * 8 + cp2;
            #pragma unroll
            for (int rh = 0; rh < 2; rh++) {
                int row = mt * 16 + r0 + rh * 8;
                long long g = (long long)(row_base + row) * DIM + col;
                float v0 = x0[g], v1 = x0[g + 1];
                xv[mt][nt][rh * 2]     = v0;
                xv[mt][nt][rh * 2 + 1] = v1;
                traj[g] = v0; traj[g + 1] = v1;
                hstore(sb + A_OFF + (uint32_t)(row * ASTRIDE + col * 2), v0, v1);
            }
            #pragma unroll
            for (int e = 0; e < 4; e++) c[mt][nt][e] = b1v[nt][e & 1];
        }

    if (times != nullptr && blockIdx.x == 0) {
        float t0 = tspan[0];
        for (int i = tid; i <= NSTEPS; i += NTHREADS)
            times[i] = t0 + 0.01f * (float)i;
    }

    const float halfdt = 0.005f;
    const float dt     = 0.01f;
    const float sixth  = (float)(0.01 / 6.0);
    const long long frame = (long long)BROWS * DIM;

    int cur = 0;                 // buffer holding the chunk about to compute
    int par0 = 0, par1 = 0, par2 = 0;   // mbarrier phase parities

    #pragma unroll 1
    for (int step = 0; step < NSTEPS; step++) {
        #pragma unroll 1
        for (int s = 0; s < 4; s++) {
            // -------- one vf eval: 4 k128 chunks (2 x W1, 2 x W2) --------
            #pragma unroll 1
            for (int t = 0; t < 4; t++) {
                // A-hazard barriers only (W readiness is per-buffer mbarrier)
                if (t == 0 || t == 2) __syncthreads();

                // issue next chunk's bulk copy (buffer freed >= 2 chunks ago;
                // ordered by the latest syncthreads, which tid0 has passed)
                int nb = cur + 1; if (nb == 3) nb = 0;
                if (tid == 0) bulk_cp((t + 1) & 3, nb, sb);

                // wait for current chunk's DMA completion
                if (cur == 0)      { MBARRIER_WAIT_PARITY(sb + MBAR_OFF + 0u,  par0); par0 ^= 1; }
                else if (cur == 1) { MBARRIER_WAIT_PARITY(sb + MBAR_OFF + 8u,  par1); par1 ^= 1; }
                else               { MBARRIER_WAIT_PARITY(sb + MBAR_OFF + 16u, par2); par2 ^= 1; }

                compute_chunk(c, sb, cur, aoff,
                              (uint32_t)(t & 1) * 256u, boff4);
                cur = nb;

                if (t == 1) {      // all warps done reading A (sync), then
                    __syncthreads();            // overwrite A with tanh(h)
                    #pragma unroll
                    for (int mt = 0; mt < 2; mt++)
                        #pragma unroll
                        for (int nt = 0; nt < 4; nt++) {
                            int col = w * 32 + nt * 8 + cp2;
                            #pragma unroll
                            for (int rh = 0; rh < 2; rh++) {
                                int row = mt * 16 + r0 + rh * 8;
                                float v0 = tanhf(c[mt][nt][rh * 2]);
                                float v1 = tanhf(c[mt][nt][rh * 2 + 1]);
                                hstore(sb + A_OFF
                                       + (uint32_t)(row * ASTRIDE + col * 2),
                                       v0, v1);
                            }
                            #pragma unroll
                            for (int e = 0; e < 4; e++)
                                c[mt][nt][e] = b2v[nt][e & 1];
                        }
                }
            }

            // -------- epi2: all warps done reading A, then RK4 combine ----
            __syncthreads();
            #pragma unroll
            for (int mt = 0; mt < 2; mt++)
                #pragma unroll
                for (int nt = 0; nt < 4; nt++) {
                    int col = w * 32 + nt * 8 + cp2;
                    #pragma unroll
                    for (int rh = 0; rh < 2; rh++) {
                        int row = mt * 16 + r0 + rh * 8;
                        float v[2];
                        #pragma unroll
                        for (int j = 0; j < 2; j++) {
                            int e = rh * 2 + j;
                            float k = c[mt][nt][e];
                            float x = xv[mt][nt][e];
                            if (s == 0) {
                                kc[mt][nt][e] = k;
                                v[j] = x + halfdt * k;
                            } else if (s == 1) {
                                kc[mt][nt][e] += 2.0f * k;
                                v[j] = x + halfdt * k;
                            } else if (s == 2) {
                                kc[mt][nt][e] += 2.0f * k;
                                v[j] = x + dt * k;
                            } else {
                                float xn = x + sixth * (kc[mt][nt][e] + k);
                                xv[mt][nt][e] = xn;
                                v[j] = xn;
                            }
                        }
                        hstore(sb + A_OFF + (uint32_t)(row * ASTRIDE + col * 2),
                               v[0], v[1]);
                        if (s == 3) {
                            long long g = (long long)(step + 1) * frame
                                        + (long long)(row_base + row) * DIM + col;
                            traj[g]     = v[0];
                            traj[g + 1] = v[1];
                        }
                    }
                    #pragma unroll
                    for (int e = 0; e < 4; e++)
                        c[mt][nt][e] = b1v[nt][e & 1];
                }
            // next chunk's t==0 __syncthreads orders these A writes
        }
    }
}

extern "C" void kernel_launch(void* const* d_in, const int* in_sizes, int n_in,
                              void* d_out, int out_size)
{
    const float* x0    = (const float*)d_in[0];
    const float* tspan = (const float*)d_in[1];
    const float* W1    = (const float*)d_in[2];
    const float* b1    = (const float*)d_in[3];
    const float* W2    = (const float*)d_in[4];
    const float* b2    = (const float*)d_in[5];

    float* out = (float*)d_out;
    const long long traj_elems = (long long)(NSTEPS + 1) * BROWS * DIM;
    float* times = nullptr;
    float* traj  = out;
    if ((long long)out_size >= traj_elems + (NSTEPS + 1)) {
        times = out;
        traj  = out + (NSTEPS + 1);
    }

    repack_kernel<<<512, 256>>>(W1, W2);

    cudaFuncSetAttribute(ode_tc_kernel,
                         cudaFuncAttributeMaxDynamicSharedMemorySize, SMEM_BYTES);
    ode_tc_kernel<<<NCTAS, NTHREADS, SMEM_BYTES>>>(x0, tspan, b1, b2, times, traj);
}

// round 15
// speedup vs baseline: 3.0382x; 1.0273x over previous
#include <cuda_runtime.h>
#include <cuda_fp16.h>
#include <cstdint>

// Neural ODE RK4 on tensor cores via mma.sync (sm_100-safe).
// B=4096, D=H=256, 100 RK4 steps. dx/dt = tanh(x@W1+b1)@W2 + b2.
// Single-term fp16 GEMMs (D = x_f16 * W_f16), fp32 accum (rel_err 1.09e-4).
//
// R15 vs R14 (1993us): barrier reduction, numerics bit-identical.
//  - A double-buffered (A_x input, A_h tanh-output): WAR barriers around the
//    epilogues vanish -> __syncthreads 4 -> 2 per vf (at chunks 0 and 2 only).
//  - W tiles stored 512B/row with XOR swizzle (col16 ^= row&7) instead of
//    528B padding, so 3 W buffers + 2 A buffers fit in 227KB smem. Swizzle is
//    baked into g_Wp by the repack kernel; cp.async.bulk stays linear.
//  - Both upcoming chunks issued together at even iters (lookahead 1-2).
//    WAR on W buffers (reuse distance 3): cp at iter t targets buffers last
//    read at compute(t-2)/(t-1), both ordered by the sync at top of t.
//
// 128 persistent CTAs x 32 rows; 8 warps; warp w owns N[w*32..) slab.
//
// Output = flattened tuple (times[101], traj[101,4096,256]); traj starts at
// byte offset 404 -> scalar 4B global stores for trajectory.

#define NSTEPS   100
#define BROWS    4096
#define DIM      256
#define MROWS    32
#define NCTAS    128
#define NTHREADS 256

#define ASTRIDE  528                 // A: bytes per padded 256-fp16 row
#define WSTRIDE  512                 // W: bytes per swizzled row
#define CHUNKB   (128 * WSTRIDE)     // k128 chunk = 65536 B
#define MBAR_OFF 0                   // 3 x 8B full-mbarriers
#define AX_OFF   64
#define AH_OFF   (AX_OFF + 16896)    // 32 rows * 528
#define W_OFF    (AH_OFF + 16896)    // 33856
#define SMEM_BYTES (W_OFF + 3 * CHUNKB)   // 230464

__device__ __align__(16) __half g_Wp[4 * 128 * 256]; // 4 chunks, swizzled

// ---------------- helpers ----------------
__device__ __forceinline__ uint32_t smem_u32(const void* p) {
    uint32_t a;
    asm("{ .reg .u64 t; cvta.to.shared.u64 t, %1; cvt.u32.u64 %0, t; }"
        : "=r"(a) : "l"(p));
    return a;
}
__device__ __forceinline__ void ldsm_x4(uint32_t r[4], uint32_t a) {
    asm volatile("ldmatrix.sync.aligned.m8n8.x4.shared.b16 {%0,%1,%2,%3}, [%4];"
                 : "=r"(r[0]), "=r"(r[1]), "=r"(r[2]), "=r"(r[3]) : "r"(a));
}
__device__ __forceinline__ void ldsm_x4t(uint32_t r[4], uint32_t a) {
    asm volatile("ldmatrix.sync.aligned.m8n8.x4.trans.shared.b16 {%0,%1,%2,%3}, [%4];"
                 : "=r"(r[0]), "=r"(r[1]), "=r"(r[2]), "=r"(r[3]) : "r"(a));
}
__device__ __forceinline__ void mma16816(float c[4], const uint32_t a[4],
                                         const uint32_t b[2]) {
    asm volatile("mma.sync.aligned.m16n8k16.row.col.f32.f16.f16.f32 "
                 "{%0,%1,%2,%3}, {%4,%5,%6,%7}, {%8,%9}, {%0,%1,%2,%3};"
                 : "+f"(c[0]), "+f"(c[1]), "+f"(c[2]), "+f"(c[3])
                 : "r"(a[0]), "r"(a[1]), "r"(a[2]), "r"(a[3]),
                   "r"(b[0]), "r"(b[1]));
}
__device__ __forceinline__ void hstore(uint32_t addr, float va, float vb) {
    __half2 h = __floats2half2_rn(va, vb);
    uint32_t u = *reinterpret_cast<uint32_t*>(&h);
    asm volatile("st.shared.b32 [%0], %1;" :: "r"(addr), "r"(u) : "memory");
}
#define MBARRIER_INIT(a, cnt) \
    asm volatile("mbarrier.init.shared.b64 [%0], %1;" :: "r"(a), "r"(cnt) : "memory")
#define MBARRIER_EXPECT_TX(a, bytes) \
    asm volatile("mbarrier.arrive.expect_tx.shared.b64 _, [%0], %1;" \
                 :: "r"(a), "r"(bytes) : "memory")
#define MBARRIER_WAIT_PARITY(mb, prty) do {                                    \
    uint32_t _m = (uint32_t)(mb), _p = (uint32_t)(prty), _d;                   \
    asm volatile("{\n\t.reg .pred p;\n\t"                                      \
        "mbarrier.try_wait.parity.acquire.cta.shared::cta.b64 p, [%1], %2;\n\t"\
        "selp.b32 %0, 1, 0, p;\n\t}" : "=r"(_d) : "r"(_m), "r"(_p) : "memory");\
    if (!_d) {                                                                 \
        asm volatile("{\n\t.reg .pred P1;\n\tWL_%=:\n\t"                       \
            "mbarrier.try_wait.parity.acquire.cta.shared::cta.b64 P1, [%0], %1, 0x989680;\n\t"\
            "@P1 bra.uni WD_%=;\n\tbra.uni WL_%=;\n\tWD_%=:\n\t}"              \
            :: "r"(_m), "r"(_p) : "memory");                                   \
    }                                                                          \
} while (0)

// ---------------- repack: W[k][n] fp32 -> fp16, swizzled 512B rows ---------
// Chunk id: mat*2 + (k>>7). Within chunk: row r=k&127, element (r,n) at
// half-index r*256 + (((n>>3) ^ (r&7))<<3) + (n&7).
__global__ void repack_kernel(const float* __restrict__ W1,
                              const float* __restrict__ W2)
{
    int t = blockIdx.x * blockDim.x + threadIdx.x;
    if (t >= 2 * DIM * DIM) return;
    int mat = t >> 16;
    int k   = (t >> 8) & 255;
    int n   = t & 255;
    float w = (mat ? W2 : W1)[k * DIM + n];
    int chunk = mat * 2 + (k >> 7);
    int r = k & 127;
    int idx = chunk * (128 * 256) + r * 256
            + ((((n >> 3) ^ (r & 7)) << 3) + (n & 7));
    g_Wp[idx] = __float2half_rn(w);
}

// ---------------- main kernel ----------------
extern __shared__ char smem_raw[];

// one cp.async.bulk of a full k128 chunk into buffer buf, completing mbar.
__device__ __forceinline__ void bulk_cp(int chunkid, int buf, uint32_t sb)
{
    uint32_t bar = sb + MBAR_OFF + (uint32_t)buf * 8u;
    uint32_t dst = sb + W_OFF + (uint32_t)buf * CHUNKB;
    const char* src = reinterpret_cast<const char*>(g_Wp)
                    + (size_t)chunkid * CHUNKB;
    MBARRIER_EXPECT_TX(bar, (uint32_t)CHUNKB);
    asm volatile("cp.async.bulk.shared::cta.global.mbarrier::complete_tx::bytes "
                 "[%0], [%1], %2, [%3];"
                 :: "r"(dst), "l"(src), "r"((uint32_t)CHUNKB), "r"(bar)
                 : "memory");
}

// one k128 chunk of the M32 x N32 (per-warp) GEMM, single-term fp16.
// abase = smem addr of this chunk's A slice (per-thread, incl. akoff).
// bconst0/1 = per-lane swizzled byte offsets for the two n8-pair ldsm.
__device__ __forceinline__ void compute_chunk(float c[2][4][4],
                                              uint32_t abase, uint32_t wb,
                                              uint32_t bconst0, uint32_t bconst1)
{
    #pragma unroll
    for (int ks = 0; ks < 8; ks++) {
        uint32_t a0[4], a1[4];
        ldsm_x4(a0, abase + (uint32_t)ks * 32u);
        ldsm_x4(a1, abase + (uint32_t)ks * 32u + 16u * ASTRIDE);

        uint32_t bb = wb + (uint32_t)ks * (16u * WSTRIDE);
        uint32_t bh[4][2];
        {
            uint32_t q[4];
            ldsm_x4t(q, bb + bconst0);
            bh[0][0] = q[0]; bh[0][1] = q[1];
            bh[1][0] = q[2]; bh[1][1] = q[3];
            ldsm_x4t(q, bb + bconst1);
            bh[2][0] = q[0]; bh[2][1] = q[1];
            bh[3][0] = q[2]; bh[3][1] = q[3];
        }
        #pragma unroll
        for (int nt = 0; nt < 4; nt++) {
            mma16816(c[0][nt], a0, bh[nt]);
            mma16816(c[1][nt], a1, bh[nt]);
        }
    }
}

__global__ void __launch_bounds__(NTHREADS, 1)
ode_tc_kernel(const float* __restrict__ x0, const float* __restrict__ tspan,
              const float* __restrict__ b1, const float* __restrict__ b2,
              float* __restrict__ times, float* __restrict__ traj)
{
    uint32_t sb = smem_u32(smem_raw);
    const int tid  = threadIdx.x;
    const int lane = tid & 31;
    const int w    = tid >> 5;
    const int r0   = lane >> 2;
    const int cp2  = (lane & 3) * 2;
    const int row_base = blockIdx.x * MROWS;

    // A ldsm per-thread byte offset (528B-padded rows)
    const uint32_t aoff = (uint32_t)(((lane & 7) + ((lane >> 3) & 1) * 8) * ASTRIDE
                                     + (lane >> 4) * 16);
    // W ldsm per-lane swizzled offsets: row = lane&15, q = w*4 + (lane>>4) + 2p
    const int wrow = lane & 15;
    const int q0   = w * 4 + ((lane >> 4) & 1);
    const uint32_t bconst0 = (uint32_t)(wrow * WSTRIDE
                             + (((q0 + 0) ^ (wrow & 7)) << 4));
    const uint32_t bconst1 = (uint32_t)(wrow * WSTRIDE
                             + (((q0 + 2) ^ (wrow & 7)) << 4));

    // mbarrier init, then prime: chunk0 -> buf0
    if (tid == 0) {
        MBARRIER_INIT(sb + MBAR_OFF + 0u, 1);
        MBARRIER_INIT(sb + MBAR_OFF + 8u, 1);
        MBARRIER_INIT(sb + MBAR_OFF + 16u, 1);
    }
    __syncthreads();
    if (tid == 0) bulk_cp(0, 0, sb);

    // biases for this thread's fixed columns
    float b1v[4][2], b2v[4][2];
    #pragma unroll
    for (int nt = 0; nt < 4; nt++) {
        int col = w * 32 + nt * 8 + cp2;
        b1v[nt][0] = b1[col];     b1v[nt][1] = b1[col + 1];
        b2v[nt][0] = b2[col];     b2v[nt][1] = b2[col + 1];
    }

    float c[2][4][4], xv[2][4][4], kc[2][4][4];

    // init: x0 -> registers + A_x tile (fp16) + trajectory frame 0
    #pragma unroll
    for (int mt = 0; mt < 2; mt++)
        #pragma unroll
        for (int nt = 0; nt < 4; nt++) {
            int col = w * 32 + nt * 8 + cp2;
            #pragma unroll
            for (int rh = 0; rh < 2; rh++) {
                int row = mt * 16 + r0 + rh * 8;
                long long g = (long long)(row_base + row) * DIM + col;
                float v0 = x0[g], v1 = x0[g + 1];
                xv[mt][nt][rh * 2]     = v0;
                xv[mt][nt][rh * 2 + 1] = v1;
                traj[g] = v0; traj[g + 1] = v1;
                hstore(sb + AX_OFF + (uint32_t)(row * ASTRIDE + col * 2), v0, v1);
            }
            #pragma unroll
            for (int e = 0; e < 4; e++) c[mt][nt][e] = b1v[nt][e & 1];
        }

    if (times != nullptr && blockIdx.x == 0) {
        float t0 = tspan[0];
        for (int i = tid; i <= NSTEPS; i += NTHREADS)
            times[i] = t0 + 0.01f * (float)i;
    }

    const float halfdt = 0.005f;
    const float dt     = 0.01f;
    const float sixth  = (float)(0.01 / 6.0);
    const long long frame = (long long)BROWS * DIM;

    int cur = 0;                        // buffer of the chunk to compute
    int par0 = 0, par1 = 0, par2 = 0;   // full-mbarrier phase parities

    #pragma unroll 1
    for (int step = 0; step < NSTEPS; step++) {
        #pragma unroll 1
        for (int s = 0; s < 4; s++) {
            // ------ one vf eval: 4 k128 chunks (W1k0,W1k1,W2k0,W2k1) ------
            #pragma unroll 1
            for (int t = 0; t < 4; t++) {
                int nb = cur + 1; if (nb == 3) nb = 0;
                if ((t & 1) == 0) {
                    // A-hazard barrier; also orders all compute(<=t-1) reads
                    // of W buffers chipwide -> safe to re-fill nb and nb2.
                    __syncthreads();
                    if (tid == 0) {
                        int nb2 = nb + 1; if (nb2 == 3) nb2 = 0;
                        bulk_cp((t + 1) & 3, nb, sb);
                        bulk_cp((t + 2) & 3, nb2, sb);
                    }
                }

                // wait for current chunk's DMA completion
                if (cur == 0)      { MBARRIER_WAIT_PARITY(sb + MBAR_OFF + 0u,  par0); par0 ^= 1; }
                else if (cur == 1) { MBARRIER_WAIT_PARITY(sb + MBAR_OFF + 8u,  par1); par1 ^= 1; }
                else               { MBARRIER_WAIT_PARITY(sb + MBAR_OFF + 16u, par2); par2 ^= 1; }

                uint32_t abase = sb + ((t < 2) ? AX_OFF : AH_OFF) + aoff
                               + (uint32_t)(t & 1) * 256u;
                compute_chunk(c, abase, sb + W_OFF + (uint32_t)cur * CHUNKB,
                              bconst0, bconst1);
                cur = nb;

                if (t == 1) {      // epi1: h = tanh(D) -> A_h (no barrier:
                                   // WAR vs prev GEMM2 reads covered by the
                                   // t==0 sync; RAW to t2 by the t==2 sync)
                    #pragma unroll
                    for (int mt = 0; mt < 2; mt++)
                        #pragma unroll
                        for (int nt = 0; nt < 4; nt++) {
                            int col = w * 32 + nt * 8 + cp2;
                            #pragma unroll
                            for (int rh = 0; rh < 2; rh++) {
                                int row = mt * 16 + r0 + rh * 8;
                                float v0 = tanhf(c[mt][nt][rh * 2]);
                                float v1 = tanhf(c[mt][nt][rh * 2 + 1]);
                                hstore(sb + AH_OFF
                                       + (uint32_t)(row * ASTRIDE + col * 2),
                                       v0, v1);
                            }
                            #pragma unroll
                            for (int e = 0; e < 4; e++)
                                c[mt][nt][e] = b2v[nt][e & 1];
                        }
                }
            }

            // ------ epi2: RK4 combine -> A_x (no barrier: WAR vs this vf's
            // GEMM1 reads covered by the t==2 sync; RAW by next t==0 sync) --
            #pragma unroll
            for (int mt = 0; mt < 2; mt++)
                #pragma unroll
                for (int nt = 0; nt < 4; nt++) {
                    int col = w * 32 + nt * 8 + cp2;
                    #pragma unroll
                    for (int rh = 0; rh < 2; rh++) {
                        int row = mt * 16 + r0 + rh * 8;
                        float v[2];
                        #pragma unroll
                        for (int j = 0; j < 2; j++) {
                            int e = rh * 2 + j;
                            float k = c[mt][nt][e];
                            float x = xv[mt][nt][e];
                            if (s == 0) {
                                kc[mt][nt][e] = k;
                                v[j] = x + halfdt * k;
                            } else if (s == 1) {
                                kc[mt][nt][e] += 2.0f * k;
                                v[j] = x + halfdt * k;
                            } else if (s == 2) {
                                kc[mt][nt][e] += 2.0f * k;
                                v[j] = x + dt * k;
                            } else {
                                float xn = x + sixth * (kc[mt][nt][e] + k);
                                xv[mt][nt][e] = xn;
                                v[j] = xn;
                            }
                        }
                        hstore(sb + AX_OFF + (uint32_t)(row * ASTRIDE + col * 2),
                               v[0], v[1]);
                        if (s == 3) {
                            long long g = (long long)(step + 1) * frame
                                        + (long long)(row_base + row) * DIM + col;
                            traj[g]     = v[0];
                            traj[g + 1] = v[1];
                        }
                    }
                    #pragma unroll
                    for (int e = 0; e < 4; e++)
                        c[mt][nt][e] = b1v[nt][e & 1];
                }
        }
    }
}

extern "C" void kernel_launch(void* const* d_in, const int* in_sizes, int n_in,
                              void* d_out, int out_size)
{
    const float* x0    = (const float*)d_in[0];
    const float* tspan = (const float*)d_in[1];
    const float* W1    = (const float*)d_in[2];
    const float* b1    = (const float*)d_in[3];
    const float* W2    = (const float*)d_in[4];
    const float* b2    = (const float*)d_in[5];

    float* out = (float*)d_out;
    const long long traj_elems = (long long)(NSTEPS + 1) * BROWS * DIM;
    float* times = nullptr;
    float* traj  = out;
    if ((long long)out_size >= traj_elems + (NSTEPS + 1)) {
        times = out;
        traj  = out + (NSTEPS + 1);
    }

    repack_kernel<<<512, 256>>>(W1, W2);

    cudaFuncSetAttribute(ode_tc_kernel,
                         cudaFuncAttributeMaxDynamicSharedMemorySize, SMEM_BYTES);
    ode_tc_kernel<<<NCTAS, NTHREADS, SMEM_BYTES>>>(x0, tspan, b1, b2, times, traj);
}

// round 16
// speedup vs baseline: 3.0846x; 1.0153x over previous
#include <cuda_runtime.h>
#include <cuda_fp16.h>
#include <cstdint>

// Neural ODE RK4 on tensor cores via mma.sync (sm_100-safe).
// B=4096, D=H=256, 100 RK4 steps. dx/dt = tanh(x@W1+b1)@W2 + b2.
// Single-term fp16 GEMMs (D = x_f16 * W_f16), fp32 accum.
//
// R16 vs R15 (1940us): latency hiding.
//  - 512 threads / 16 warps per CTA (4 warps/SMSP, was 2). M-split: warps
//    0-7 own rows 0..15, warps 8-15 rows 16..31; N32 slab per warp as before.
//    Per-warp fragments halve (fits 128-reg cap), per-SMSP MMA count is
//    unchanged, but ldsm/HMMA latency is now hidden by 4-way interleave.
//  - tanh.approx.f32 (MUFU.TANH) in epi1 (error ~ fp16 h-rounding, in budget).
//
// W tiles: 512B rows, XOR swizzle (col16 ^= row&7) baked into g_Wp; loaded
// with one cp.async.bulk per k128 chunk into a 3-buffer ring (mbarrier
// complete_tx). A double-buffered (A_x / A_h) -> only 2 __syncthreads per vf.
//
// Output = flattened tuple (times[101], traj[101,4096,256]); traj starts at
// byte offset 404 -> scalar 4B global stores for trajectory.

#define NSTEPS   100
#define BROWS    4096
#define DIM      256
#define MROWS    32
#define NCTAS    128
#define NTHREADS 512

#define ASTRIDE  528                 // A: bytes per padded 256-fp16 row
#define WSTRIDE  512                 // W: bytes per swizzled row
#define CHUNKB   (128 * WSTRIDE)     // k128 chunk = 65536 B
#define MBAR_OFF 0                   // 3 x 8B full-mbarriers
#define AX_OFF   64
#define AH_OFF   (AX_OFF + 16896)    // 32 rows * 528
#define W_OFF    (AH_OFF + 16896)    // 33856
#define SMEM_BYTES (W_OFF + 3 * CHUNKB)   // 230464

__device__ __align__(16) __half g_Wp[4 * 128 * 256]; // 4 chunks, swizzled

// ---------------- helpers ----------------
__device__ __forceinline__ uint32_t smem_u32(const void* p) {
    uint32_t a;
    asm("{ .reg .u64 t; cvta.to.shared.u64 t, %1; cvt.u32.u64 %0, t; }"
        : "=r"(a) : "l"(p));
    return a;
}
__device__ __forceinline__ void ldsm_x4(uint32_t r[4], uint32_t a) {
    asm volatile("ldmatrix.sync.aligned.m8n8.x4.shared.b16 {%0,%1,%2,%3}, [%4];"
                 : "=r"(r[0]), "=r"(r[1]), "=r"(r[2]), "=r"(r[3]) : "r"(a));
}
__device__ __forceinline__ void ldsm_x4t(uint32_t r[4], uint32_t a) {
    asm volatile("ldmatrix.sync.aligned.m8n8.x4.trans.shared.b16 {%0,%1,%2,%3}, [%4];"
                 : "=r"(r[0]), "=r"(r[1]), "=r"(r[2]), "=r"(r[3]) : "r"(a));
}
__device__ __forceinline__ void mma16816(float c[4], const uint32_t a[4],
                                         const uint32_t b[2]) {
    asm volatile("mma.sync.aligned.m16n8k16.row.col.f32.f16.f16.f32 "
                 "{%0,%1,%2,%3}, {%4,%5,%6,%7}, {%8,%9}, {%0,%1,%2,%3};"
                 : "+f"(c[0]), "+f"(c[1]), "+f"(c[2]), "+f"(c[3])
                 : "r"(a[0]), "r"(a[1]), "r"(a[2]), "r"(a[3]),
                   "r"(b[0]), "r"(b[1]));
}
__device__ __forceinline__ void hstore(uint32_t addr, float va, float vb) {
    __half2 h = __floats2half2_rn(va, vb);
    uint32_t u = *reinterpret_cast<uint32_t*>(&h);
    asm volatile("st.shared.b32 [%0], %1;" :: "r"(addr), "r"(u) : "memory");
}
__device__ __forceinline__ float tanh_fast(float x) {
    float y;
    asm("tanh.approx.f32 %0, %1;" : "=f"(y) : "f"(x));
    return y;
}
#define MBARRIER_INIT(a, cnt) \
    asm volatile("mbarrier.init.shared.b64 [%0], %1;" :: "r"(a), "r"(cnt) : "memory")
#define MBARRIER_EXPECT_TX(a, bytes) \
    asm volatile("mbarrier.arrive.expect_tx.shared.b64 _, [%0], %1;" \
                 :: "r"(a), "r"(bytes) : "memory")
#define MBARRIER_WAIT_PARITY(mb, prty) do {                                    \
    uint32_t _m = (uint32_t)(mb), _p = (uint32_t)(prty), _d;                   \
    asm volatile("{\n\t.reg .pred p;\n\t"                                      \
        "mbarrier.try_wait.parity.acquire.cta.shared::cta.b64 p, [%1], %2;\n\t"\
        "selp.b32 %0, 1, 0, p;\n\t}" : "=r"(_d) : "r"(_m), "r"(_p) : "memory");\
    if (!_d) {                                                                 \
        asm volatile("{\n\t.reg .pred P1;\n\tWL_%=:\n\t"                       \
            "mbarrier.try_wait.parity.acquire.cta.shared::cta.b64 P1, [%0], %1, 0x989680;\n\t"\
            "@P1 bra.uni WD_%=;\n\tbra.uni WL_%=;\n\tWD_%=:\n\t}"              \
            :: "r"(_m), "r"(_p) : "memory");                                   \
    }                                                                          \
} while (0)

// ---------------- repack: W[k][n] fp32 -> fp16, swizzled 512B rows ---------
__global__ void repack_kernel(const float* __restrict__ W1,
                              const float* __restrict__ W2)
{
    int t = blockIdx.x * blockDim.x + threadIdx.x;
    if (t >= 2 * DIM * DIM) return;
    int mat = t >> 16;
    int k   = (t >> 8) & 255;
    int n   = t & 255;
    float w = (mat ? W2 : W1)[k * DIM + n];
    int chunk = mat * 2 + (k >> 7);
    int r = k & 127;
    int idx = chunk * (128 * 256) + r * 256
            + ((((n >> 3) ^ (r & 7)) << 3) + (n & 7));
    g_Wp[idx] = __float2half_rn(w);
}

// ---------------- main kernel ----------------
extern __shared__ char smem_raw[];

__device__ __forceinline__ void bulk_cp(int chunkid, int buf, uint32_t sb)
{
    uint32_t bar = sb + MBAR_OFF + (uint32_t)buf * 8u;
    uint32_t dst = sb + W_OFF + (uint32_t)buf * CHUNKB;
    const char* src = reinterpret_cast<const char*>(g_Wp)
                    + (size_t)chunkid * CHUNKB;
    MBARRIER_EXPECT_TX(bar, (uint32_t)CHUNKB);
    asm volatile("cp.async.bulk.shared::cta.global.mbarrier::complete_tx::bytes "
                 "[%0], [%1], %2, [%3];"
                 :: "r"(dst), "l"(src), "r"((uint32_t)CHUNKB), "r"(bar)
                 : "memory");
}

// one k128 chunk of the per-warp M16 x N32 GEMM, single-term fp16.
__device__ __forceinline__ void compute_chunk(float c[4][4],
                                              uint32_t abase, uint32_t wb,
                                              uint32_t bconst0, uint32_t bconst1)
{
    #pragma unroll
    for (int ks = 0; ks < 8; ks++) {
        uint32_t a0[4];
        ldsm_x4(a0, abase + (uint32_t)ks * 32u);

        uint32_t bb = wb + (uint32_t)ks * (16u * WSTRIDE);
        uint32_t bh[4][2];
        {
            uint32_t q[4];
            ldsm_x4t(q, bb + bconst0);
            bh[0][0] = q[0]; bh[0][1] = q[1];
            bh[1][0] = q[2]; bh[1][1] = q[3];
            ldsm_x4t(q, bb + bconst1);
            bh[2][0] = q[0]; bh[2][1] = q[1];
            bh[3][0] = q[2]; bh[3][1] = q[3];
        }
        #pragma unroll
        for (int nt = 0; nt < 4; nt++)
            mma16816(c[nt], a0, bh[nt]);
    }
}

__global__ void __launch_bounds__(NTHREADS, 1)
ode_tc_kernel(const float* __restrict__ x0, const float* __restrict__ tspan,
              const float* __restrict__ b1, const float* __restrict__ b2,
              float* __restrict__ times, float* __restrict__ traj)
{
    uint32_t sb = smem_u32(smem_raw);
    const int tid   = threadIdx.x;
    const int lane  = tid & 31;
    const int w     = tid >> 5;        // 0..15
    const int wslab = w & 7;           // N-slab id
    const int mbase = (w >> 3) * 16;   // M-half base row
    const int r0    = lane >> 2;
    const int cp2   = (lane & 3) * 2;
    const int row_base = blockIdx.x * MROWS;

    // A ldsm per-thread byte offset (m16 fragment), incl. M-half base
    const uint32_t aoff = (uint32_t)((mbase + (lane & 15)) * ASTRIDE
                                     + (lane >> 4) * 16);
    // W ldsm per-lane swizzled offsets
    const int wrow = lane & 15;
    const int q0   = wslab * 4 + ((lane >> 4) & 1);
    const uint32_t bconst0 = (uint32_t)(wrow * WSTRIDE
                             + (((q0 + 0) ^ (wrow & 7)) << 4));
    const uint32_t bconst1 = (uint32_t)(wrow * WSTRIDE
                             + (((q0 + 2) ^ (wrow & 7)) << 4));

    // mbarrier init, then prime: chunk0 -> buf0
    if (tid == 0) {
        MBARRIER_INIT(sb + MBAR_OFF + 0u, 1);
        MBARRIER_INIT(sb + MBAR_OFF + 8u, 1);
        MBARRIER_INIT(sb + MBAR_OFF + 16u, 1);
    }
    __syncthreads();
    if (tid == 0) bulk_cp(0, 0, sb);

    // biases for this thread's fixed columns
    float b1v[4][2], b2v[4][2];
    #pragma unroll
    for (int nt = 0; nt < 4; nt++) {
        int col = wslab * 32 + nt * 8 + cp2;
        b1v[nt][0] = b1[col];     b1v[nt][1] = b1[col + 1];
        b2v[nt][0] = b2[col];     b2v[nt][1] = b2[col + 1];
    }

    float c[4][4], xv[4][4], kc[4][4];

    // init: x0 -> registers + A_x tile (fp16) + trajectory frame 0
    #pragma unroll
    for (int nt = 0; nt < 4; nt++) {
        int col = wslab * 32 + nt * 8 + cp2;
        #pragma unroll
        for (int rh = 0; rh < 2; rh++) {
            int row = mbase + r0 + rh * 8;
            long long g = (long long)(row_base + row) * DIM + col;
            float v0 = x0[g], v1 = x0[g + 1];
            xv[nt][rh * 2]     = v0;
            xv[nt][rh * 2 + 1] = v1;
            traj[g] = v0; traj[g + 1] = v1;
            hstore(sb + AX_OFF + (uint32_t)(row * ASTRIDE + col * 2), v0, v1);
        }
        #pragma unroll
        for (int e = 0; e < 4; e++) c[nt][e] = b1v[nt][e & 1];
    }

    if (times != nullptr && blockIdx.x == 0) {
        float t0 = tspan[0];
        for (int i = tid; i <= NSTEPS; i += NTHREADS)
            times[i] = t0 + 0.01f * (float)i;
    }

    const float halfdt = 0.005f;
    const float dt     = 0.01f;
    const float sixth  = (float)(0.01 / 6.0);
    const long long frame = (long long)BROWS * DIM;

    int cur = 0;                        // buffer of the chunk to compute
    int par0 = 0, par1 = 0, par2 = 0;   // full-mbarrier phase parities

    #pragma unroll 1
    for (int step = 0; step < NSTEPS; step++) {
        #pragma unroll 1
        for (int s = 0; s < 4; s++) {
            // ------ one vf eval: 4 k128 chunks (W1k0,W1k1,W2k0,W2k1) ------
            #pragma unroll 1
            for (int t = 0; t < 4; t++) {
                int nb = cur + 1; if (nb == 3) nb = 0;
                if ((t & 1) == 0) {
                    // A-hazard barrier; also orders all prior W-buffer reads
                    __syncthreads();
                    if (tid == 0) {
                        int nb2 = nb + 1; if (nb2 == 3) nb2 = 0;
                        bulk_cp((t + 1) & 3, nb, sb);
                        bulk_cp((t + 2) & 3, nb2, sb);
                    }
                }

                // wait for current chunk's DMA completion
                if (cur == 0)      { MBARRIER_WAIT_PARITY(sb + MBAR_OFF + 0u,  par0); par0 ^= 1; }
                else if (cur == 1) { MBARRIER_WAIT_PARITY(sb + MBAR_OFF + 8u,  par1); par1 ^= 1; }
                else               { MBARRIER_WAIT_PARITY(sb + MBAR_OFF + 16u, par2); par2 ^= 1; }

                uint32_t abase = sb + ((t < 2) ? AX_OFF : AH_OFF) + aoff
                               + (uint32_t)(t & 1) * 256u;
                compute_chunk(c, abase, sb + W_OFF + (uint32_t)cur * CHUNKB,
                              bconst0, bconst1);
                cur = nb;

                if (t == 1) {      // epi1: h = tanh(D) -> A_h (MUFU.TANH)
                    #pragma unroll
                    for (int nt = 0; nt < 4; nt++) {
                        int col = wslab * 32 + nt * 8 + cp2;
                        #pragma unroll
                        for (int rh = 0; rh < 2; rh++) {
                            int row = mbase + r0 + rh * 8;
                            float v0 = tanh_fast(c[nt][rh * 2]);
                            float v1 = tanh_fast(c[nt][rh * 2 + 1]);
                            hstore(sb + AH_OFF
                                   + (uint32_t)(row * ASTRIDE + col * 2),
                                   v0, v1);
                        }
                        #pragma unroll
                        for (int e = 0; e < 4; e++)
                            c[nt][e] = b2v[nt][e & 1];
                    }
                }
            }

            // ------ epi2: RK4 combine -> A_x ------
            #pragma unroll
            for (int nt = 0; nt < 4; nt++) {
                int col = wslab * 32 + nt * 8 + cp2;
                #pragma unroll
                for (int rh = 0; rh < 2; rh++) {
                    int row = mbase + r0 + rh * 8;
                    float v[2];
                    #pragma unroll
                    for (int j = 0; j < 2; j++) {
                        int e = rh * 2 + j;
                        float k = c[nt][e];
                        float x = xv[nt][e];
                        if (s == 0) {
                            kc[nt][e] = k;
                            v[j] = x + halfdt * k;
                        } else if (s == 1) {
                            kc[nt][e] += 2.0f * k;
                            v[j] = x + halfdt * k;
                        } else if (s == 2) {
                            kc[nt][e] += 2.0f * k;
                            v[j] = x + dt * k;
                        } else {
                            float xn = x + sixth * (kc[nt][e] + k);
                            xv[nt][e] = xn;
                            v[j] = xn;
                        }
                    }
                    hstore(sb + AX_OFF + (uint32_t)(row * ASTRIDE + col * 2),
                           v[0], v[1]);
                    if (s == 3) {
                        long long g = (long long)(step + 1) * frame
                                    + (long long)(row_base + row) * DIM + col;
                        traj[g]     = v[0];
                        traj[g + 1] = v[1];
                    }
                }
                #pragma unroll
                for (int e = 0; e < 4; e++)
                    c[nt][e] = b1v[nt][e & 1];
            }
        }
    }
}

extern "C" void kernel_launch(void* const* d_in, const int* in_sizes, int n_in,
                              void* d_out, int out_size)
{
    const float* x0    = (const float*)d_in[0];
    const float* tspan = (const float*)d_in[1];
    const float* W1    = (const float*)d_in[2];
    const float* b1    = (const float*)d_in[3];
    const float* W2    = (const float*)d_in[4];
    const float* b2    = (const float*)d_in[5];

    float* out = (float*)d_out;
    const long long traj_elems = (long long)(NSTEPS + 1) * BROWS * DIM;
    float* times = nullptr;
    float* traj  = out;
    if ((long long)out_size >= traj_elems + (NSTEPS + 1)) {
        times = out;
        traj  = out + (NSTEPS + 1);
    }

    repack_kernel<<<512, 256>>>(W1, W2);

    cudaFuncSetAttribute(ode_tc_kernel,
                         cudaFuncAttributeMaxDynamicSharedMemorySize, SMEM_BYTES);
    ode_tc_kernel<<<NCTAS, NTHREADS, SMEM_BYTES>>>(x0, tspan, b1, b2, times, traj);
}

// round 17
// speedup vs baseline: 3.1756x; 1.0295x over previous
#include <cuda_runtime.h>
#include <cuda_fp16.h>
#include <cstdint>

// Neural ODE RK4 on tensor cores via mma.sync (sm_100-safe).
// B=4096, D=H=256, 100 RK4 steps. dx/dt = tanh(x@W1+b1)@W2 + b2.
// Single-term fp16 GEMMs (D = x_f16 * W_f16), fp32 accum.
//
// R17 vs R16 (1911us): instruction-overhead pass, numerics bit-identical.
//  - t-chunk loop fully unrolled (compile-time pruning of parity/epi branches)
//  - epi2 stage-specialized (template<int S>) -> straight-line FMA, no
//    per-element 4-way branch
// Measured context: sm_100 mma.sync m16n8k16(f32 acc) issues ~1/16cyc/SMSP
// (invariant across 2 vs 4 warps/SMSP); floor 1.72ms, R16 at 94% of it.
//
// 128 persistent CTAs x 32 rows; 16 warps (M-split halves x 8 N-slabs).
// W tiles: 512B rows, XOR swizzle (col16 ^= row&7) baked into g_Wp; one
// cp.async.bulk per k128 chunk into a 3-buffer ring (mbarrier complete_tx).
// A double-buffered (A_x / A_h) -> 2 __syncthreads per vf eval.
//
// Output = flattened tuple (times[101], traj[101,4096,256]); traj starts at
// byte offset 404 -> scalar 4B global stores for trajectory.

#define NSTEPS   100
#define BROWS    4096
#define DIM      256
#define MROWS    32
#define NCTAS    128
#define NTHREADS 512

#define ASTRIDE  528                 // A: bytes per padded 256-fp16 row
#define WSTRIDE  512                 // W: bytes per swizzled row
#define CHUNKB   (128 * WSTRIDE)     // k128 chunk = 65536 B
#define MBAR_OFF 0                   // 3 x 8B full-mbarriers
#define AX_OFF   64
#define AH_OFF   (AX_OFF + 16896)    // 32 rows * 528
#define W_OFF    (AH_OFF + 16896)    // 33856
#define SMEM_BYTES (W_OFF + 3 * CHUNKB)   // 230464

__device__ __align__(16) __half g_Wp[4 * 128 * 256]; // 4 chunks, swizzled

// ---------------- helpers ----------------
__device__ __forceinline__ uint32_t smem_u32(const void* p) {
    uint32_t a;
    asm("{ .reg .u64 t; cvta.to.shared.u64 t, %1; cvt.u32.u64 %0, t; }"
        : "=r"(a) : "l"(p));
    return a;
}
__device__ __forceinline__ void ldsm_x4(uint32_t r[4], uint32_t a) {
    asm volatile("ldmatrix.sync.aligned.m8n8.x4.shared.b16 {%0,%1,%2,%3}, [%4];"
                 : "=r"(r[0]), "=r"(r[1]), "=r"(r[2]), "=r"(r[3]) : "r"(a));
}
__device__ __forceinline__ void ldsm_x4t(uint32_t r[4], uint32_t a) {
    asm volatile("ldmatrix.sync.aligned.m8n8.x4.trans.shared.b16 {%0,%1,%2,%3}, [%4];"
                 : "=r"(r[0]), "=r"(r[1]), "=r"(r[2]), "=r"(r[3]) : "r"(a));
}
__device__ __forceinline__ void mma16816(float c[4], const uint32_t a[4],
                                         const uint32_t b[2]) {
    asm volatile("mma.sync.aligned.m16n8k16.row.col.f32.f16.f16.f32 "
                 "{%0,%1,%2,%3}, {%4,%5,%6,%7}, {%8,%9}, {%0,%1,%2,%3};"
                 : "+f"(c[0]), "+f"(c[1]), "+f"(c[2]), "+f"(c[3])
                 : "r"(a[0]), "r"(a[1]), "r"(a[2]), "r"(a[3]),
                   "r"(b[0]), "r"(b[1]));
}
__device__ __forceinline__ void hstore(uint32_t addr, float va, float vb) {
    __half2 h = __floats2half2_rn(va, vb);
    uint32_t u = *reinterpret_cast<uint32_t*>(&h);
    asm volatile("st.shared.b32 [%0], %1;" :: "r"(addr), "r"(u) : "memory");
}
__device__ __forceinline__ float tanh_fast(float x) {
    float y;
    asm("tanh.approx.f32 %0, %1;" : "=f"(y) : "f"(x));
    return y;
}
#define MBARRIER_INIT(a, cnt) \
    asm volatile("mbarrier.init.shared.b64 [%0], %1;" :: "r"(a), "r"(cnt) : "memory")
#define MBARRIER_EXPECT_TX(a, bytes) \
    asm volatile("mbarrier.arrive.expect_tx.shared.b64 _, [%0], %1;" \
                 :: "r"(a), "r"(bytes) : "memory")
#define MBARRIER_WAIT_PARITY(mb, prty) do {                                    \
    uint32_t _m = (uint32_t)(mb), _p = (uint32_t)(prty), _d;                   \
    asm volatile("{\n\t.reg .pred p;\n\t"                                      \
        "mbarrier.try_wait.parity.acquire.cta.shared::cta.b64 p, [%1], %2;\n\t"\
        "selp.b32 %0, 1, 0, p;\n\t}" : "=r"(_d) : "r"(_m), "r"(_p) : "memory");\
    if (!_d) {                                                                 \
        asm volatile("{\n\t.reg .pred P1;\n\tWL_%=:\n\t"                       \
            "mbarrier.try_wait.parity.acquire.cta.shared::cta.b64 P1, [%0], %1, 0x989680;\n\t"\
            "@P1 bra.uni WD_%=;\n\tbra.uni WL_%=;\n\tWD_%=:\n\t}"              \
            :: "r"(_m), "r"(_p) : "memory");                                   \
    }                                                                          \
} while (0)

// ---------------- repack: W[k][n] fp32 -> fp16, swizzled 512B rows ---------
__global__ void repack_kernel(const float* __restrict__ W1,
                              const float* __restrict__ W2)
{
    int t = blockIdx.x * blockDim.x + threadIdx.x;
    if (t >= 2 * DIM * DIM) return;
    int mat = t >> 16;
    int k   = (t >> 8) & 255;
    int n   = t & 255;
    float w = (mat ? W2 : W1)[k * DIM + n];
    int chunk = mat * 2 + (k >> 7);
    int r = k & 127;
    int idx = chunk * (128 * 256) + r * 256
            + ((((n >> 3) ^ (r & 7)) << 3) + (n & 7));
    g_Wp[idx] = __float2half_rn(w);
}

// ---------------- main kernel ----------------
extern __shared__ char smem_raw[];

__device__ __forceinline__ void bulk_cp(int chunkid, int buf, uint32_t sb)
{
    uint32_t bar = sb + MBAR_OFF + (uint32_t)buf * 8u;
    uint32_t dst = sb + W_OFF + (uint32_t)buf * CHUNKB;
    const char* src = reinterpret_cast<const char*>(g_Wp)
                    + (size_t)chunkid * CHUNKB;
    MBARRIER_EXPECT_TX(bar, (uint32_t)CHUNKB);
    asm volatile("cp.async.bulk.shared::cta.global.mbarrier::complete_tx::bytes "
                 "[%0], [%1], %2, [%3];"
                 :: "r"(dst), "l"(src), "r"((uint32_t)CHUNKB), "r"(bar)
                 : "memory");
}

// one k128 chunk of the per-warp M16 x N32 GEMM, single-term fp16.
__device__ __forceinline__ void compute_chunk(float c[4][4],
                                              uint32_t abase, uint32_t wb,
                                              uint32_t bconst0, uint32_t bconst1)
{
    #pragma unroll
    for (int ks = 0; ks < 8; ks++) {
        uint32_t a0[4];
        ldsm_x4(a0, abase + (uint32_t)ks * 32u);

        uint32_t bb = wb + (uint32_t)ks * (16u * WSTRIDE);
        uint32_t bh[4][2];
        {
            uint32_t q[4];
            ldsm_x4t(q, bb + bconst0);
            bh[0][0] = q[0]; bh[0][1] = q[1];
            bh[1][0] = q[2]; bh[1][1] = q[3];
            ldsm_x4t(q, bb + bconst1);
            bh[2][0] = q[0]; bh[2][1] = q[1];
            bh[3][0] = q[2]; bh[3][1] = q[3];
        }
        #pragma unroll
        for (int nt = 0; nt < 4; nt++)
            mma16816(c[nt], a0, bh[nt]);
    }
}

// stage-specialized RK4 epilogue 2: straight-line per stage S.
template<int S>
__device__ __forceinline__ void rk4_epi(
    float c[4][4], float xv[4][4], float kc[4][4],
    const float b1v[4][2], uint32_t sb,
    int wslab, int mbase, int r0, int cp2,
    long long grow_base, float* __restrict__ traj)
{
    const float halfdt = 0.005f;
    const float dt     = 0.01f;
    const float sixth  = (float)(0.01 / 6.0);
    #pragma unroll
    for (int nt = 0; nt < 4; nt++) {
        int col = wslab * 32 + nt * 8 + cp2;
        #pragma unroll
        for (int rh = 0; rh < 2; rh++) {
            int row = mbase + r0 + rh * 8;
            float v[2];
            #pragma unroll
            for (int j = 0; j < 2; j++) {
                int e = rh * 2 + j;
                float k = c[nt][e];
                float x = xv[nt][e];
                if (S == 0) {
                    kc[nt][e] = k;
                    v[j] = fmaf(halfdt, k, x);
                } else if (S == 1) {
                    kc[nt][e] = fmaf(2.0f, k, kc[nt][e]);
                    v[j] = fmaf(halfdt, k, x);
                } else if (S == 2) {
                    kc[nt][e] = fmaf(2.0f, k, kc[nt][e]);
                    v[j] = fmaf(dt, k, x);
                } else {
                    float xn = x + sixth * (kc[nt][e] + k);
                    xv[nt][e] = xn;
                    v[j] = xn;
                }
            }
            hstore(sb + AX_OFF + (uint32_t)(row * ASTRIDE + col * 2),
                   v[0], v[1]);
            if (S == 3) {
                long long g = grow_base + (long long)row * DIM + col;
                traj[g]     = v[0];
                traj[g + 1] = v[1];
            }
        }
        #pragma unroll
        for (int e = 0; e < 4; e++)
            c[nt][e] = b1v[nt][e & 1];
    }
}

__global__ void __launch_bounds__(NTHREADS, 1)
ode_tc_kernel(const float* __restrict__ x0, const float* __restrict__ tspan,
              const float* __restrict__ b1, const float* __restrict__ b2,
              float* __restrict__ times, float* __restrict__ traj)
{
    uint32_t sb = smem_u32(smem_raw);
    const int tid   = threadIdx.x;
    const int lane  = tid & 31;
    const int w     = tid >> 5;        // 0..15
    const int wslab = w & 7;           // N-slab id
    const int mbase = (w >> 3) * 16;   // M-half base row
    const int r0    = lane >> 2;
    const int cp2   = (lane & 3) * 2;
    const int row_base = blockIdx.x * MROWS;

    // A ldsm per-thread byte offset (m16 fragment), incl. M-half base
    const uint32_t aoff = (uint32_t)((mbase + (lane & 15)) * ASTRIDE
                                     + (lane >> 4) * 16);
    // W ldsm per-lane swizzled offsets
    const int wrow = lane & 15;
    const int q0   = wslab * 4 + ((lane >> 4) & 1);
    const uint32_t bconst0 = (uint32_t)(wrow * WSTRIDE
                             + (((q0 + 0) ^ (wrow & 7)) << 4));
    const uint32_t bconst1 = (uint32_t)(wrow * WSTRIDE
                             + (((q0 + 2) ^ (wrow & 7)) << 4));

    // mbarrier init, then prime: chunk0 -> buf0
    if (tid == 0) {
        MBARRIER_INIT(sb + MBAR_OFF + 0u, 1);
        MBARRIER_INIT(sb + MBAR_OFF + 8u, 1);
        MBARRIER_INIT(sb + MBAR_OFF + 16u, 1);
    }
    __syncthreads();
    if (tid == 0) bulk_cp(0, 0, sb);

    // biases for this thread's fixed columns
    float b1v[4][2], b2v[4][2];
    #pragma unroll
    for (int nt = 0; nt < 4; nt++) {
        int col = wslab * 32 + nt * 8 + cp2;
        b1v[nt][0] = b1[col];     b1v[nt][1] = b1[col + 1];
        b2v[nt][0] = b2[col];     b2v[nt][1] = b2[col + 1];
    }

    float c[4][4], xv[4][4], kc[4][4];

    // init: x0 -> registers + A_x tile (fp16) + trajectory frame 0
    #pragma unroll
    for (int nt = 0; nt < 4; nt++) {
        int col = wslab * 32 + nt * 8 + cp2;
        #pragma unroll
        for (int rh = 0; rh < 2; rh++) {
            int row = mbase + r0 + rh * 8;
            long long g = (long long)(row_base + row) * DIM + col;
            float v0 = x0[g], v1 = x0[g + 1];
            xv[nt][rh * 2]     = v0;
            xv[nt][rh * 2 + 1] = v1;
            traj[g] = v0; traj[g + 1] = v1;
            hstore(sb + AX_OFF + (uint32_t)(row * ASTRIDE + col * 2), v0, v1);
        }
        #pragma unroll
        for (int e = 0; e < 4; e++) c[nt][e] = b1v[nt][e & 1];
    }

    if (times != nullptr && blockIdx.x == 0) {
        float t0 = tspan[0];
        for (int i = tid; i <= NSTEPS; i += NTHREADS)
            times[i] = t0 + 0.01f * (float)i;
    }

    const long long frame = (long long)BROWS * DIM;

    int cur = 0;                        // buffer of the chunk to compute
    int par0 = 0, par1 = 0, par2 = 0;   // full-mbarrier phase parities

    #pragma unroll 1
    for (int step = 0; step < NSTEPS; step++) {
        #pragma unroll 1
        for (int s = 0; s < 4; s++) {
            // ------ one vf eval: 4 k128 chunks, t-loop fully unrolled ------
            #pragma unroll
            for (int t = 0; t < 4; t++) {
                int nb = cur + 1; if (nb == 3) nb = 0;
                if ((t & 1) == 0) {
                    // A-hazard barrier; also orders all prior W-buffer reads
                    __syncthreads();
                    if (tid == 0) {
                        int nb2 = nb + 1; if (nb2 == 3) nb2 = 0;
                        bulk_cp((t + 1) & 3, nb, sb);
                        bulk_cp((t + 2) & 3, nb2, sb);
                    }
                }

                // wait for current chunk's DMA completion
                if (cur == 0)      { MBARRIER_WAIT_PARITY(sb + MBAR_OFF + 0u,  par0); par0 ^= 1; }
                else if (cur == 1) { MBARRIER_WAIT_PARITY(sb + MBAR_OFF + 8u,  par1); par1 ^= 1; }
                else               { MBARRIER_WAIT_PARITY(sb + MBAR_OFF + 16u, par2); par2 ^= 1; }

                uint32_t abase = sb + ((t < 2) ? AX_OFF : AH_OFF) + aoff
                               + (uint32_t)(t & 1) * 256u;
                compute_chunk(c, abase, sb + W_OFF + (uint32_t)cur * CHUNKB,
                              bconst0, bconst1);
                cur = nb;

                if (t == 1) {      // epi1: h = tanh(D) -> A_h (MUFU.TANH)
                    #pragma unroll
                    for (int nt = 0; nt < 4; nt++) {
                        int col = wslab * 32 + nt * 8 + cp2;
                        #pragma unroll
                        for (int rh = 0; rh < 2; rh++) {
                            int row = mbase + r0 + rh * 8;
                            float v0 = tanh_fast(c[nt][rh * 2]);
                            float v1 = tanh_fast(c[nt][rh * 2 + 1]);
                            hstore(sb + AH_OFF
                                   + (uint32_t)(row * ASTRIDE + col * 2),
                                   v0, v1);
                        }
                        #pragma unroll
                        for (int e = 0; e < 4; e++)
                            c[nt][e] = b2v[nt][e & 1];
                    }
                }
            }

            // ------ epi2: stage-specialized RK4 combine -> A_x ------
            long long gb = (long long)(step + 1) * frame
                         + (long long)row_base * DIM;
            if (s == 0)      rk4_epi<0>(c, xv, kc, b1v, sb, wslab, mbase, r0, cp2, gb, traj);
            else if (s == 1) rk4_epi<1>(c, xv, kc, b1v, sb, wslab, mbase, r0, cp2, gb, traj);
            else if (s == 2) rk4_epi<2>(c, xv, kc, b1v, sb, wslab, mbase, r0, cp2, gb, traj);
            else             rk4_epi<3>(c, xv, kc, b1v, sb, wslab, mbase, r0, cp2, gb, traj);
        }
    }
}

extern "C" void kernel_launch(void* const* d_in, const int* in_sizes, int n_in,
                              void* d_out, int out_size)
{
    const float* x0    = (const float*)d_in[0];
    const float* tspan = (const float*)d_in[1];
    const float* W1    = (const float*)d_in[2];
    const float* b1    = (const float*)d_in[3];
    const float* W2    = (const float*)d_in[4];
    const float* b2    = (const float*)d_in[5];

    float* out = (float*)d_out;
    const long long traj_elems = (long long)(NSTEPS + 1) * BROWS * DIM;
    float* times = nullptr;
    float* traj  = out;
    if ((long long)out_size >= traj_elems + (NSTEPS + 1)) {
        times = out;
        traj  = out + (NSTEPS + 1);
    }

    repack_kernel<<<512, 256>>>(W1, W2);

    cudaFuncSetAttribute(ode_tc_kernel,
                         cudaFuncAttributeMaxDynamicSharedMemorySize, SMEM_BYTES);
    ode_tc_kernel<<<NCTAS, NTHREADS, SMEM_BYTES>>>(x0, tspan, b1, b2, times, traj);
}